// round 10
// baseline (speedup 1.0000x reference)
#include <cuda_runtime.h>
#include <cstdint>
#include <math.h>

// Problem constants
#define B_    2
#define S_    2048
#define HID_  4096
#define H_    32
#define KVH_  8
#define D_    128
#define NREP  (H_/KVH_)                 // 4
#define QKVN  (HID_ + 2*KVH_*D_)        // 6144
#define MTOK  (B_*S_)                   // 4096

// Scratch (static device globals; no runtime allocation allowed)
__device__ float g_qkv[(size_t)MTOK * QKVN];            // [tok][6144] fp32
__device__ float g_q  [(size_t)B_*H_*S_*D_];            // tf32 bits, pre-scaled
__device__ float g_k  [(size_t)B_*KVH_*S_*D_];          // tf32 bits
__device__ float g_v  [(size_t)B_*KVH_*S_*D_];          // tf32 bits
__device__ float g_ao [(size_t)MTOK * H_*D_];           // tf32 bits
__device__ float g_ht [(size_t)MTOK * HID_];            // hidden, tf32 bits
__device__ float g_w1 [(size_t)QKVN * HID_];            // qkv_w, tf32 bits
__device__ float g_w2 [(size_t)HID_ * HID_];            // o_w, tf32 bits

__device__ __forceinline__ uint32_t f2tf32(float f) {
    uint32_t r;
    asm("cvt.rna.tf32.f32 %0, %1;" : "=r"(r) : "f"(f));
    return r;
}
__device__ __forceinline__ float ex2f(float x) {
    float y;
    asm("ex2.approx.f32 %0, %1;" : "=f"(y) : "f"(x));
    return y;
}
__device__ __forceinline__ void mma_tf32(float* c, const uint32_t* a, const uint32_t* b) {
    asm volatile(
        "mma.sync.aligned.m16n8k8.row.col.f32.tf32.tf32.f32 "
        "{%0,%1,%2,%3}, {%4,%5,%6,%7}, {%8,%9}, {%0,%1,%2,%3};"
        : "+f"(c[0]), "+f"(c[1]), "+f"(c[2]), "+f"(c[3])
        : "r"(a[0]), "r"(a[1]), "r"(a[2]), "r"(a[3]), "r"(b[0]), "r"(b[1]));
}
__device__ __forceinline__ void cp_async16(uint32_t saddr, const void* gaddr) {
    asm volatile("cp.async.cg.shared.global [%0], [%1], 16;"
                 :: "r"(saddr), "l"(gaddr) : "memory");
}

// ---------------------------------------------------------------------------
// One-time tf32 pre-convert (elementwise, vectorized)
// ---------------------------------------------------------------------------
__global__ __launch_bounds__(256) void cvt_tf32(
    const float* __restrict__ in, float* __restrict__ out, int n4)
{
    int i = blockIdx.x * 256 + threadIdx.x;
    if (i >= n4) return;
    float4 v = ((const float4*)in)[i];
    uint4 u;
    u.x = f2tf32(v.x); u.y = f2tf32(v.y); u.z = f2tf32(v.z); u.w = f2tf32(v.w);
    ((uint4*)out)[i] = u;
}

// ===========================================================================
// tf32 mma.sync GEMM (NT): C = A * B^T, inputs pre-rounded tf32 bits.
// CTA tile 128x64, 4 warps (2x2), warp tile 64x32 (10.7 FLOP/byte of LDS).
// BK=16, 3-stage cp.async. launch_bounds(128,5) -> 5 CTAs/SM = 20 warps in
// 5 independent barrier groups: reuse of R4 + occupancy of R9.
// ===========================================================================
#define GBM 128
#define GBN 64
#define GBK 16
#define GSTRIDE 20
#define GA_FLOATS (GBM * GSTRIDE)               // 2560
#define GB_FLOATS (GBN * GSTRIDE)               // 1280
#define G_STAGE_FLOATS (GA_FLOATS + GB_FLOATS)  // 3840 floats = 15360 B
#define G_NSTAGE 3
#define G_DYN_SMEM (G_NSTAGE * G_STAGE_FLOATS * 4)   // 46080 bytes

__global__ __launch_bounds__(128, 5) void gemm_mma(
    const float* __restrict__ A, const float* __restrict__ Bm,
    float* __restrict__ C, int M, int N, int K)
{
    extern __shared__ float sdyn[];
    const uint32_t sbase = (uint32_t)__cvta_generic_to_shared(sdyn);

    const int tid  = threadIdx.x;
    const int wid  = tid >> 5;
    const int lane = tid & 31;
    const int warp_m = wid >> 1;          // 0..1 (64 rows each)
    const int warp_n = wid & 1;           // 0..1 (32 cols each)
    const int lane4 = lane >> 2;          // 0..7
    const int lanek = lane & 3;           // 0..3
    const int m0 = blockIdx.y * GBM;
    const int n0 = blockIdx.x * GBN;
    const int NK = K >> 4;

    // Global->smem: A row = tid (4 chunks); B row = tid>>1 (2 chunks)
    const int rb  = tid >> 1;
    const int cb  = (tid & 1) * 2;
    const float* Ag = A  + (size_t)(m0 + tid) * K;
    const float* Bg = Bm + (size_t)(n0 + rb) * K;
    const uint32_t sArow = sbase + (uint32_t)tid * (GSTRIDE * 4);
    const uint32_t sBrow = sbase + GA_FLOATS * 4 + (uint32_t)rb * (GSTRIDE * 4);

    // Prologue: fill stages 0,1
#pragma unroll
    for (int s = 0; s < G_NSTAGE - 1; s++) {
        uint32_t so = (uint32_t)s * (G_STAGE_FLOATS * 4);
#pragma unroll
        for (int j = 0; j < 4; j++)
            cp_async16(sArow + so + j * 16, Ag + s * GBK + j * 4);
        cp_async16(sBrow + so + (cb    ) * 16, Bg + s * GBK + (cb    ) * 4);
        cp_async16(sBrow + so + (cb + 1) * 16, Bg + s * GBK + (cb + 1) * 4);
        asm volatile("cp.async.commit_group;" ::: "memory");
    }

    float acc[4][4][4];
#pragma unroll
    for (int i = 0; i < 4; i++)
#pragma unroll
        for (int j = 0; j < 4; j++)
#pragma unroll
            for (int t = 0; t < 4; t++) acc[i][j][t] = 0.f;

    const int arow_off = (warp_m * 64 + lane4) * GSTRIDE + lanek;
    const int brow_off = (warp_n * 32 + lane4) * GSTRIDE + lanek;

    for (int it = 0; it < NK; it++) {
        asm volatile("cp.async.wait_group %0;" :: "n"(G_NSTAGE - 2) : "memory");
        __syncthreads();

        int itn = it + G_NSTAGE - 1;
        if (itn < NK) {
            uint32_t so = (uint32_t)(itn % G_NSTAGE) * (G_STAGE_FLOATS * 4);
#pragma unroll
            for (int j = 0; j < 4; j++)
                cp_async16(sArow + so + j * 16, Ag + itn * GBK + j * 4);
            cp_async16(sBrow + so + (cb    ) * 16, Bg + itn * GBK + (cb    ) * 4);
            cp_async16(sBrow + so + (cb + 1) * 16, Bg + itn * GBK + (cb + 1) * 4);
        }
        asm volatile("cp.async.commit_group;" ::: "memory");

        const uint32_t* sA = (const uint32_t*)(sdyn + (it % G_NSTAGE) * G_STAGE_FLOATS);
        const uint32_t* sB = sA + GA_FLOATS;

#pragma unroll
        for (int ks = 0; ks < 2; ks++) {
            const int kb = ks * 8;
            uint32_t af[4][4], bf[4][2];
#pragma unroll
            for (int mt = 0; mt < 4; mt++) {
                const uint32_t* ap = sA + arow_off + mt * (16 * GSTRIDE) + kb;
                af[mt][0] = ap[0];
                af[mt][1] = ap[8 * GSTRIDE];
                af[mt][2] = ap[4];
                af[mt][3] = ap[8 * GSTRIDE + 4];
            }
#pragma unroll
            for (int nt = 0; nt < 4; nt++) {
                const uint32_t* bp = sB + brow_off + nt * (8 * GSTRIDE) + kb;
                bf[nt][0] = bp[0];
                bf[nt][1] = bp[4];
            }
#pragma unroll
            for (int mt = 0; mt < 4; mt++)
#pragma unroll
                for (int nt = 0; nt < 4; nt++)
                    mma_tf32(acc[mt][nt], af[mt], bf[nt]);
        }
    }

#pragma unroll
    for (int mt = 0; mt < 4; mt++) {
#pragma unroll
        for (int nt = 0; nt < 4; nt++) {
            int row = m0 + warp_m * 64 + mt * 16 + lane4;
            int col = n0 + warp_n * 32 + nt * 8 + lanek * 2;
            *(float2*)&C[(size_t)row * N + col] =
                make_float2(acc[mt][nt][0], acc[mt][nt][1]);
            *(float2*)&C[(size_t)(row + 8) * N + col] =
                make_float2(acc[mt][nt][2], acc[mt][nt][3]);
        }
    }
}

// ---------------------------------------------------------------------------
// RoPE + per-head RMSNorm + scatter, one block per TOKEN. (unchanged from R9)
// ---------------------------------------------------------------------------
__global__ __launch_bounds__(128) void rope_norm(
    const float* __restrict__ cosb, const float* __restrict__ sinb,
    const float* __restrict__ qw,   const float* __restrict__ kw)
{
    const int tok = blockIdx.x;
    const int b = tok / S_, s = tok % S_;
    const int tid = threadIdx.x;
    const int w = tid >> 5, lane = tid & 31;
    const float QSC = 0.08838834764831845f * 1.4426950408889634f;

    const float* row = g_qkv + (size_t)tok * QKVN;
    float c4[4], s4[4], qw4[4], kw4[4];
#pragma unroll
    for (int j = 0; j < 4; j++) {
        int d = lane + 32 * j;
        c4[j]  = cosb[((size_t)b * S_ + s) * D_ + d];
        s4[j]  = sinb[((size_t)b * S_ + s) * D_ + d];
        qw4[j] = qw[d];
        kw4[j] = kw[d];
    }

    for (int hh = w; hh < H_ + KVH_; hh += 4) {
        int off = (hh < H_) ? hh * D_ : H_ * D_ + (hh - H_) * D_;
        float x[4], y[4];
#pragma unroll
        for (int j = 0; j < 4; j++) x[j] = row[off + lane + 32 * j];
        y[0] = x[0] * c4[0] - x[2] * s4[0];
        y[1] = x[1] * c4[1] - x[3] * s4[1];
        y[2] = x[2] * c4[2] + x[0] * s4[2];
        y[3] = x[3] * c4[3] + x[1] * s4[3];
        float v2 = y[0] * y[0] + y[1] * y[1] + y[2] * y[2] + y[3] * y[3];
#pragma unroll
        for (int o = 16; o; o >>= 1) v2 += __shfl_xor_sync(0xffffffffu, v2, o);
        float inv = rsqrtf(v2 * (1.f / D_) + 1e-6f);

        if (hh < H_) {
            uint32_t* dst = (uint32_t*)g_q + (((size_t)b * H_ + hh) * S_ + s) * D_;
#pragma unroll
            for (int j = 0; j < 4; j++)
                dst[lane + 32 * j] = f2tf32(qw4[j] * y[j] * inv * QSC);
        } else {
            uint32_t* dst = (uint32_t*)g_k +
                (((size_t)b * KVH_ + (hh - H_)) * S_ + s) * D_;
#pragma unroll
            for (int j = 0; j < 4; j++)
                dst[lane + 32 * j] = f2tf32(kw4[j] * y[j] * inv);
        }
    }

    for (int kv = w; kv < KVH_; kv += 4) {
        const float* src = row + H_ * D_ + KVH_ * D_ + kv * D_;
        uint32_t* dst = (uint32_t*)g_v + (((size_t)b * KVH_ + kv) * S_ + s) * D_;
#pragma unroll
        for (int j = 0; j < 4; j++)
            dst[lane + 32 * j] = f2tf32(src[lane + 32 * j]);
    }
}

// ---------------------------------------------------------------------------
// Flash attention, tf32 mma.sync, SPLIT-D over 16 warps (512 threads).
// BR=128, BC=64, D=128. Warp pair (w, w+8) owns the same 16 q-rows:
//   QK: w computes d 0..63 (kk 0..7), w+8 computes d 64..127; partials merged
//       through sS. Softmax in low warps only; cr handed to high warps via sCr.
//   PV: w produces output d 0..63 (nt 0..7), w+8 d 64..127 (nt 8..15).
// Occupancy: 16 warps/SM (was 8).
// ---------------------------------------------------------------------------
#define FBR 128
#define ADP 132
#define APP 68
#define SQ_F   (FBR * ADP)          // 16896
#define SK_F   (64 * ADP)           // 8448
#define SV_F   (64 * ADP)           // 8448
#define SP_F   (8 * 16 * APP)       // 8704
#define SS_F   (8 * 16 * APP)       // 8704
#define SCR_F  (8 * 16)             // 128
#define SINV_F (8 * 16)             // 128
#define ATTN_SMEM ((SQ_F + SK_F + SV_F + SP_F + SS_F + SCR_F + SINV_F) * 4)

__global__ __launch_bounds__(512) void flash_attn_mma(float* __restrict__ AO)
{
    extern __shared__ float sm[];
    float* sQ   = sm;                       // 128 x 132
    float* sK   = sQ + SQ_F;                // 64 x 132
    float* sV   = sK + SK_F;                // 64 x 132
    float* sP   = sV + SV_F;                // 8 x (16 x 68)
    float* sS   = sP + SP_F;                // 8 x (16 x 68) score partials
    float* sCr  = sS + SS_F;                // 8 x 16 correction factors
    float* sInv = sCr + SCR_F;              // 8 x 16 final 1/l

    const int b  = blockIdx.z, h = blockIdx.y;
    const int q0 = blockIdx.x * FBR;
    const int kh = h / NREP;
    const float* Qg = g_q + (((size_t)b * H_ + h) * S_ + q0) * D_;
    const float* Kg = g_k + ((size_t)b * KVH_ + kh) * (size_t)S_ * D_;
    const float* Vg = g_v + ((size_t)b * KVH_ + kh) * (size_t)S_ * D_;

    const int tid  = threadIdx.x;
    const int w    = tid >> 5;            // 0..15
    const int wl   = w & 7;               // row-group id (shared by w, w+8)
    const bool hi  = (w >= 8);
    const int lane = tid & 31;
    const int lane4 = lane >> 2;
    const int lanek = lane & 3;

    // Q: tf32 bits, pre-scaled: straight copy (128 x 128 -> padded smem)
    for (int e = tid; e < FBR * 32; e += 512) {
        int r = e >> 5, c = e & 31;
        *(float4*)&sQ[r * ADP + c * 4] = ((const float4*)Qg)[r * 32 + c];
    }

    // Each warp outputs 16 rows x 64 d-columns
    float oacc[8][4];
#pragma unroll
    for (int nt = 0; nt < 8; nt++)
#pragma unroll
        for (int t = 0; t < 4; t++) oacc[nt][t] = 0.f;
    float m0 = -1e30f, m1 = -1e30f, l0 = 0.f, l1 = 0.f;   // low warps only

    const uint32_t* sQu = (const uint32_t*)sQ;
    const uint32_t* sKu = (const uint32_t*)sK;
    const uint32_t* sVu = (const uint32_t*)sV;
    uint32_t* sPw = (uint32_t*)sP + wl * (16 * APP);
    float*    sSw = sS + wl * (16 * APP);

    const int kk0 = hi ? 8 : 0;      // d-half for QK
    const int nt0 = hi ? 8 : 0;      // d-half for PV output

    for (int t0 = 0; t0 < S_; t0 += 64) {
        __syncthreads();   // (A) prev-iter PV reads of sP/sV done; sK/sS free
        for (int e = tid; e < 64 * 32; e += 512) {
            int r = e >> 5, c = e & 31;
            *(float4*)&sK[r * ADP + c * 4] = ((const float4*)(Kg + (size_t)t0 * D_))[r * 32 + c];
            *(float4*)&sV[r * ADP + c * 4] = ((const float4*)(Vg + (size_t)t0 * D_))[r * 32 + c];
        }
        __syncthreads();   // (B) K/V tiles ready

        // ---- QK^T over this warp's d-half
        float sc[8][4];
#pragma unroll
        for (int nt = 0; nt < 8; nt++)
#pragma unroll
            for (int t = 0; t < 4; t++) sc[nt][t] = 0.f;

#pragma unroll
        for (int kx = 0; kx < 8; kx++) {
            const int kk = kk0 + kx;
            uint32_t a[4];
            const uint32_t* qp = sQu + (wl * 16 + lane4) * ADP + kk * 8 + lanek;
            a[0] = qp[0]; a[1] = qp[8 * ADP]; a[2] = qp[4]; a[3] = qp[8 * ADP + 4];
#pragma unroll
            for (int nt = 0; nt < 8; nt++) {
                uint32_t bb[2];
                const uint32_t* kp = sKu + (nt * 8 + lane4) * ADP + kk * 8 + lanek;
                bb[0] = kp[0]; bb[1] = kp[4];
                mma_tf32(sc[nt], a, bb);
            }
        }

        // High warps publish their partial scores
        if (hi) {
#pragma unroll
            for (int nt = 0; nt < 8; nt++) {
                *(float2*)&sSw[lane4 * APP + nt * 8 + 2 * lanek] =
                    make_float2(sc[nt][0], sc[nt][1]);
                *(float2*)&sSw[(lane4 + 8) * APP + nt * 8 + 2 * lanek] =
                    make_float2(sc[nt][2], sc[nt][3]);
            }
        }
        __syncthreads();   // (C) partials ready

        if (!hi) {
            // merge partials (32-bit loads: conflict-free with stride 68)
#pragma unroll
            for (int nt = 0; nt < 8; nt++) {
                const float* p0 = sSw + lane4 * APP + nt * 8 + 2 * lanek;
                const float* p1 = sSw + (lane4 + 8) * APP + nt * 8 + 2 * lanek;
                sc[nt][0] += p0[0]; sc[nt][1] += p0[1];
                sc[nt][2] += p1[0]; sc[nt][3] += p1[1];
            }

            // ---- online softmax (log2 domain)
            float mx0 = -1e30f, mx1 = -1e30f;
#pragma unroll
            for (int nt = 0; nt < 8; nt++) {
                mx0 = fmaxf(mx0, fmaxf(sc[nt][0], sc[nt][1]));
                mx1 = fmaxf(mx1, fmaxf(sc[nt][2], sc[nt][3]));
            }
            mx0 = fmaxf(mx0, __shfl_xor_sync(0xffffffffu, mx0, 1));
            mx0 = fmaxf(mx0, __shfl_xor_sync(0xffffffffu, mx0, 2));
            mx1 = fmaxf(mx1, __shfl_xor_sync(0xffffffffu, mx1, 1));
            mx1 = fmaxf(mx1, __shfl_xor_sync(0xffffffffu, mx1, 2));
            float mn0 = fmaxf(m0, mx0), mn1 = fmaxf(m1, mx1);
            float cr0 = ex2f(m0 - mn0), cr1 = ex2f(m1 - mn1);

            float s0 = 0.f, s1 = 0.f;
#pragma unroll
            for (int nt = 0; nt < 8; nt++) {
                float p00 = ex2f(sc[nt][0] - mn0);
                float p01 = ex2f(sc[nt][1] - mn0);
                float p10 = ex2f(sc[nt][2] - mn1);
                float p11 = ex2f(sc[nt][3] - mn1);
                s0 += p00 + p01;
                s1 += p10 + p11;
                *(uint2*)&sPw[lane4 * APP + nt * 8 + 2 * lanek] =
                    make_uint2(f2tf32(p00), f2tf32(p01));
                *(uint2*)&sPw[(lane4 + 8) * APP + nt * 8 + 2 * lanek] =
                    make_uint2(f2tf32(p10), f2tf32(p11));
            }
            s0 += __shfl_xor_sync(0xffffffffu, s0, 1);
            s0 += __shfl_xor_sync(0xffffffffu, s0, 2);
            s1 += __shfl_xor_sync(0xffffffffu, s1, 1);
            s1 += __shfl_xor_sync(0xffffffffu, s1, 2);
            l0 = l0 * cr0 + s0;
            l1 = l1 * cr1 + s1;
            m0 = mn0; m1 = mn1;

            if (lanek == 0) {
                sCr[wl * 16 + lane4]     = cr0;
                sCr[wl * 16 + lane4 + 8] = cr1;
            }
        }
        __syncthreads();   // (D) P + cr ready

        float c0, c1;
        if (!hi) {
            c0 = sCr[wl * 16 + lane4];      // same value we wrote; uniform path
            c1 = sCr[wl * 16 + lane4 + 8];
        } else {
            c0 = sCr[wl * 16 + lane4];
            c1 = sCr[wl * 16 + lane4 + 8];
        }
#pragma unroll
        for (int nt = 0; nt < 8; nt++) {
            oacc[nt][0] *= c0; oacc[nt][1] *= c0;
            oacc[nt][2] *= c1; oacc[nt][3] *= c1;
        }

        // ---- P @ V over this warp's output d-half
#pragma unroll
        for (int kk = 0; kk < 8; kk++) {
            uint32_t a[4];
            const uint32_t* pp = sPw + lane4 * APP + kk * 8 + lanek;
            a[0] = pp[0]; a[1] = pp[8 * APP]; a[2] = pp[4]; a[3] = pp[8 * APP + 4];
#pragma unroll
            for (int nx = 0; nx < 8; nx++) {
                const int nt = nt0 + nx;
                uint32_t bb[2];
                const uint32_t* vp = sVu + (kk * 8 + lanek) * ADP + nt * 8 + lane4;
                bb[0] = vp[0]; bb[1] = vp[4 * ADP];
                mma_tf32(oacc[nx], a, bb);
            }
        }
    }

    // Publish 1/l from low warps, then everyone normalizes & writes its half.
    if (!hi && lanek == 0) {
        sInv[wl * 16 + lane4]     = 1.f / l0;
        sInv[wl * 16 + lane4 + 8] = 1.f / l1;
    }
    __syncthreads();
    float i0 = sInv[wl * 16 + lane4];
    float i1 = sInv[wl * 16 + lane4 + 8];

    int row0 = q0 + wl * 16 + lane4;
    uint32_t* O0 = (uint32_t*)AO + ((size_t)(b * S_ + row0) * H_ + h) * D_;
    uint32_t* O1 = O0 + (size_t)8 * H_ * D_;
#pragma unroll
    for (int nx = 0; nx < 8; nx++) {
        int col = (nt0 + nx) * 8 + 2 * lanek;
        *(uint2*)&O0[col] = make_uint2(f2tf32(oacc[nx][0] * i0), f2tf32(oacc[nx][1] * i0));
        *(uint2*)&O1[col] = make_uint2(f2tf32(oacc[nx][2] * i1), f2tf32(oacc[nx][3] * i1));
    }
}

// ---------------------------------------------------------------------------
extern "C" void kernel_launch(void* const* d_in, const int* in_sizes, int n_in,
                              void* d_out, int out_size)
{
    const float* hidden = (const float*)d_in[0];
    const float* cosb   = (const float*)d_in[1];
    const float* sinb   = (const float*)d_in[2];
    const float* qkv_w  = (const float*)d_in[3];
    const float* o_w    = (const float*)d_in[4];
    const float* qnw    = (const float*)d_in[5];
    const float* knw    = (const float*)d_in[6];
    float* out = (float*)d_out;

    float *qkvp, *aop, *htp, *w1p, *w2p;
    cudaGetSymbolAddress((void**)&qkvp, g_qkv);
    cudaGetSymbolAddress((void**)&aop,  g_ao);
    cudaGetSymbolAddress((void**)&htp,  g_ht);
    cudaGetSymbolAddress((void**)&w1p,  g_w1);
    cudaGetSymbolAddress((void**)&w2p,  g_w2);

    cudaFuncSetAttribute(gemm_mma, cudaFuncAttributeMaxDynamicSharedMemorySize,
                         G_DYN_SMEM);
    cudaFuncSetAttribute(flash_attn_mma, cudaFuncAttributeMaxDynamicSharedMemorySize,
                         ATTN_SMEM);

    // 0) One-time tf32 pre-convert of GEMM inputs
    int nh = MTOK * HID_ / 4, nw1 = QKVN * HID_ / 4, nw2 = HID_ * HID_ / 4;
    cvt_tf32<<<(nh  + 255) / 256, 256>>>(hidden, htp, nh);
    cvt_tf32<<<(nw1 + 255) / 256, 256>>>(qkv_w,  w1p, nw1);
    cvt_tf32<<<(nw2 + 255) / 256, 256>>>(o_w,    w2p, nw2);

    // 1) QKV projection (tf32 mma.sync, 64x32 warp tile, 5 CTAs/SM)
    dim3 g1(QKVN / GBN, MTOK / GBM);
    gemm_mma<<<g1, 128, G_DYN_SMEM>>>(htp, w1p, qkvp, MTOK, QKVN, HID_);

    // 2) RoPE + RMSNorm + scatter (one block per token)
    rope_norm<<<MTOK, 128>>>(cosb, sinb, qnw, knw);

    // 3) Attention (split-D, 16 warps)
    dim3 g3(S_ / FBR, H_, B_);
    flash_attn_mma<<<g3, 512, ATTN_SMEM>>>(aop);

    // 4) O projection
    dim3 g4(HID_ / GBN, MTOK / GBM);
    gemm_mma<<<g4, 128, G_DYN_SMEM>>>(aop, w2p, out, MTOK, HID_, H_ * D_);
}

// round 11
// speedup vs baseline: 1.1181x; 1.1181x over previous
#include <cuda_runtime.h>
#include <cstdint>
#include <math.h>

// Problem constants
#define B_    2
#define S_    2048
#define HID_  4096
#define H_    32
#define KVH_  8
#define D_    128
#define NREP  (H_/KVH_)                 // 4
#define QKVN  (HID_ + 2*KVH_*D_)        // 6144
#define MTOK  (B_*S_)                   // 4096

// Scratch (static device globals; no runtime allocation allowed)
__device__ float g_qkv[(size_t)MTOK * QKVN];            // [tok][6144] fp32
__device__ float g_q  [(size_t)B_*H_*S_*D_];            // tf32 bits, pre-scaled
__device__ float g_k  [(size_t)B_*KVH_*S_*D_];          // tf32 bits
__device__ float g_v  [(size_t)B_*KVH_*S_*D_];          // tf32 bits
__device__ float g_ao [(size_t)MTOK * H_*D_];           // tf32 bits
__device__ float g_ht [(size_t)MTOK * HID_];            // hidden, tf32 bits
__device__ float g_w1 [(size_t)QKVN * HID_];            // qkv_w, tf32 bits
__device__ float g_w2 [(size_t)HID_ * HID_];            // o_w, tf32 bits

__device__ __forceinline__ uint32_t f2tf32(float f) {
    uint32_t r;
    asm("cvt.rna.tf32.f32 %0, %1;" : "=r"(r) : "f"(f));
    return r;
}
__device__ __forceinline__ float ex2f(float x) {
    float y;
    asm("ex2.approx.f32 %0, %1;" : "=f"(y) : "f"(x));
    return y;
}
__device__ __forceinline__ void mma_tf32(float* c, const uint32_t* a, const uint32_t* b) {
    asm volatile(
        "mma.sync.aligned.m16n8k8.row.col.f32.tf32.tf32.f32 "
        "{%0,%1,%2,%3}, {%4,%5,%6,%7}, {%8,%9}, {%0,%1,%2,%3};"
        : "+f"(c[0]), "+f"(c[1]), "+f"(c[2]), "+f"(c[3])
        : "r"(a[0]), "r"(a[1]), "r"(a[2]), "r"(a[3]), "r"(b[0]), "r"(b[1]));
}
__device__ __forceinline__ void cp_async16(uint32_t saddr, const void* gaddr) {
    asm volatile("cp.async.cg.shared.global [%0], [%1], 16;"
                 :: "r"(saddr), "l"(gaddr) : "memory");
}

// ---------------------------------------------------------------------------
// One-time tf32 pre-convert (elementwise, vectorized)
// ---------------------------------------------------------------------------
__global__ __launch_bounds__(256) void cvt_tf32(
    const float* __restrict__ in, float* __restrict__ out, int n4)
{
    int i = blockIdx.x * 256 + threadIdx.x;
    if (i >= n4) return;
    float4 v = ((const float4*)in)[i];
    uint4 u;
    u.x = f2tf32(v.x); u.y = f2tf32(v.y); u.z = f2tf32(v.z); u.w = f2tf32(v.w);
    ((uint4*)out)[i] = u;
}

// ===========================================================================
// tf32 mma.sync GEMM (NT): C = A * B^T, inputs pre-rounded tf32 bits.
// CTA tile 128x128, 8 warps (2x4), warp tile 64x32 => 272 crossbar-bytes/MMA
// (A 128 + B 64 + STS 80). BK=16, 3-stage cp.async, 61.4KB smem =>
// 3 CTAs/SM (24 warps). launch_bounds(256,3): 85-reg cap; MMA loop is
// structured so live set = 64 acc + 8 bf + 4 af + addr ~= 84 (no spills).
// ===========================================================================
#define GBM 128
#define GBN 128
#define GBK 16
#define GSTRIDE 20
#define GA_FLOATS (GBM * GSTRIDE)               // 2560
#define GB_FLOATS (GBN * GSTRIDE)               // 2560
#define G_STAGE_FLOATS (GA_FLOATS + GB_FLOATS)  // 5120 floats = 20480 B
#define G_NSTAGE 3
#define G_DYN_SMEM (G_NSTAGE * G_STAGE_FLOATS * 4)   // 61440 bytes

__global__ __launch_bounds__(256, 3) void gemm_mma(
    const float* __restrict__ A, const float* __restrict__ Bm,
    float* __restrict__ C, int M, int N, int K)
{
    extern __shared__ float sdyn[];
    const uint32_t sbase = (uint32_t)__cvta_generic_to_shared(sdyn);

    const int tid  = threadIdx.x;
    const int wid  = tid >> 5;
    const int lane = tid & 31;
    const int warp_m = wid >> 2;          // 0..1 (64 rows)
    const int warp_n = wid & 3;           // 0..3 (32 cols)
    const int lane4 = lane >> 2;          // 0..7
    const int lanek = lane & 3;           // 0..3
    const int m0 = blockIdx.y * GBM;
    const int n0 = blockIdx.x * GBN;
    const int NK = K >> 4;

    // Global->smem: row r = tid/2, two 16B chunks per operand (R4 loader)
    const int r  = tid >> 1;
    const int c0 = (tid & 1) * 2;
    const float* Ag = A  + (size_t)(m0 + r) * K;
    const float* Bg = Bm + (size_t)(n0 + r) * K;
    const uint32_t sArow = sbase + (uint32_t)r * (GSTRIDE * 4);
    const uint32_t sBrow = sArow + GA_FLOATS * 4;

    // Prologue: fill stages 0,1
#pragma unroll
    for (int s = 0; s < G_NSTAGE - 1; s++) {
        uint32_t so = (uint32_t)s * (G_STAGE_FLOATS * 4);
        cp_async16(sArow + so + (c0    ) * 16, Ag + s * GBK + (c0    ) * 4);
        cp_async16(sArow + so + (c0 + 1) * 16, Ag + s * GBK + (c0 + 1) * 4);
        cp_async16(sBrow + so + (c0    ) * 16, Bg + s * GBK + (c0    ) * 4);
        cp_async16(sBrow + so + (c0 + 1) * 16, Bg + s * GBK + (c0 + 1) * 4);
        asm volatile("cp.async.commit_group;" ::: "memory");
    }

    float acc[4][4][4];
#pragma unroll
    for (int i = 0; i < 4; i++)
#pragma unroll
        for (int j = 0; j < 4; j++)
#pragma unroll
            for (int t = 0; t < 4; t++) acc[i][j][t] = 0.f;

    const int arow_off = (warp_m * 64 + lane4) * GSTRIDE + lanek;
    const int brow_off = (warp_n * 32 + lane4) * GSTRIDE + lanek;

    for (int it = 0; it < NK; it++) {
        asm volatile("cp.async.wait_group %0;" :: "n"(G_NSTAGE - 2) : "memory");
        __syncthreads();

        int itn = it + G_NSTAGE - 1;
        if (itn < NK) {
            uint32_t so = (uint32_t)(itn % G_NSTAGE) * (G_STAGE_FLOATS * 4);
            cp_async16(sArow + so + (c0    ) * 16, Ag + itn * GBK + (c0    ) * 4);
            cp_async16(sArow + so + (c0 + 1) * 16, Ag + itn * GBK + (c0 + 1) * 4);
            cp_async16(sBrow + so + (c0    ) * 16, Bg + itn * GBK + (c0    ) * 4);
            cp_async16(sBrow + so + (c0 + 1) * 16, Bg + itn * GBK + (c0 + 1) * 4);
        }
        asm volatile("cp.async.commit_group;" ::: "memory");

        const uint32_t* sA = (const uint32_t*)(sdyn + (it % G_NSTAGE) * G_STAGE_FLOATS);
        const uint32_t* sB = sA + GA_FLOATS;

#pragma unroll
        for (int ks = 0; ks < 2; ks++) {
            const int kb = ks * 8;
            // B fragments for this ks (8 regs live)
            uint32_t bf[4][2];
#pragma unroll
            for (int nt = 0; nt < 4; nt++) {
                const uint32_t* bp = sB + brow_off + nt * (8 * GSTRIDE) + kb;
                bf[nt][0] = bp[0];
                bf[nt][1] = bp[4];
            }
            // A fragment per mt (only 4 regs live at a time)
#pragma unroll
            for (int mt = 0; mt < 4; mt++) {
                uint32_t af[4];
                const uint32_t* ap = sA + arow_off + mt * (16 * GSTRIDE) + kb;
                af[0] = ap[0];
                af[1] = ap[8 * GSTRIDE];
                af[2] = ap[4];
                af[3] = ap[8 * GSTRIDE + 4];
#pragma unroll
                for (int nt = 0; nt < 4; nt++)
                    mma_tf32(acc[mt][nt], af, bf[nt]);
            }
        }
    }

#pragma unroll
    for (int mt = 0; mt < 4; mt++) {
#pragma unroll
        for (int nt = 0; nt < 4; nt++) {
            int row = m0 + warp_m * 64 + mt * 16 + lane4;
            int col = n0 + warp_n * 32 + nt * 8 + lanek * 2;
            *(float2*)&C[(size_t)row * N + col] =
                make_float2(acc[mt][nt][0], acc[mt][nt][1]);
            *(float2*)&C[(size_t)(row + 8) * N + col] =
                make_float2(acc[mt][nt][2], acc[mt][nt][3]);
        }
    }
}

// ---------------------------------------------------------------------------
// RoPE + per-head RMSNorm + scatter, one block per TOKEN (R9 version).
// ---------------------------------------------------------------------------
__global__ __launch_bounds__(128) void rope_norm(
    const float* __restrict__ cosb, const float* __restrict__ sinb,
    const float* __restrict__ qw,   const float* __restrict__ kw)
{
    const int tok = blockIdx.x;
    const int b = tok / S_, s = tok % S_;
    const int tid = threadIdx.x;
    const int w = tid >> 5, lane = tid & 31;
    const float QSC = 0.08838834764831845f * 1.4426950408889634f;

    const float* row = g_qkv + (size_t)tok * QKVN;
    float c4[4], s4[4], qw4[4], kw4[4];
#pragma unroll
    for (int j = 0; j < 4; j++) {
        int d = lane + 32 * j;
        c4[j]  = cosb[((size_t)b * S_ + s) * D_ + d];
        s4[j]  = sinb[((size_t)b * S_ + s) * D_ + d];
        qw4[j] = qw[d];
        kw4[j] = kw[d];
    }

    for (int hh = w; hh < H_ + KVH_; hh += 4) {
        int off = (hh < H_) ? hh * D_ : H_ * D_ + (hh - H_) * D_;
        float x[4], y[4];
#pragma unroll
        for (int j = 0; j < 4; j++) x[j] = row[off + lane + 32 * j];
        y[0] = x[0] * c4[0] - x[2] * s4[0];
        y[1] = x[1] * c4[1] - x[3] * s4[1];
        y[2] = x[2] * c4[2] + x[0] * s4[2];
        y[3] = x[3] * c4[3] + x[1] * s4[3];
        float v2 = y[0] * y[0] + y[1] * y[1] + y[2] * y[2] + y[3] * y[3];
#pragma unroll
        for (int o = 16; o; o >>= 1) v2 += __shfl_xor_sync(0xffffffffu, v2, o);
        float inv = rsqrtf(v2 * (1.f / D_) + 1e-6f);

        if (hh < H_) {
            uint32_t* dst = (uint32_t*)g_q + (((size_t)b * H_ + hh) * S_ + s) * D_;
#pragma unroll
            for (int j = 0; j < 4; j++)
                dst[lane + 32 * j] = f2tf32(qw4[j] * y[j] * inv * QSC);
        } else {
            uint32_t* dst = (uint32_t*)g_k +
                (((size_t)b * KVH_ + (hh - H_)) * S_ + s) * D_;
#pragma unroll
            for (int j = 0; j < 4; j++)
                dst[lane + 32 * j] = f2tf32(kw4[j] * y[j] * inv);
        }
    }

    for (int kv = w; kv < KVH_; kv += 4) {
        const float* src = row + H_ * D_ + KVH_ * D_ + kv * D_;
        uint32_t* dst = (uint32_t*)g_v + (((size_t)b * KVH_ + kv) * S_ + s) * D_;
#pragma unroll
        for (int j = 0; j < 4; j++)
            dst[lane + 32 * j] = f2tf32(src[lane + 32 * j]);
    }
}

// ---------------------------------------------------------------------------
// Flash attention with tf32 mma.sync (R9 version). BR=128 (8 warps, 256 thr),
// BC=64, D=128. Inputs pre-converted tf32 bits. Output tf32 bits -> g_ao.
// ---------------------------------------------------------------------------
#define FBR 128
#define ADP 132
#define APP 68
#define ATTN_SMEM ((FBR * ADP + 2 * 64 * ADP + 8 * 16 * APP) * 4)  // 169984 B

__global__ __launch_bounds__(256) void flash_attn_mma(float* __restrict__ AO)
{
    extern __shared__ float sm[];
    float* sQ = sm;                        // 128 x 132
    float* sK = sQ + FBR * ADP;            // 64 x 132
    float* sV = sK + 64 * ADP;             // 64 x 132
    float* sP = sV + 64 * ADP;             // 8 warps x 16 x 68

    const int b  = blockIdx.z, h = blockIdx.y;
    const int q0 = blockIdx.x * FBR;
    const int kh = h / NREP;
    const float* Qg = g_q + (((size_t)b * H_ + h) * S_ + q0) * D_;
    const float* Kg = g_k + ((size_t)b * KVH_ + kh) * (size_t)S_ * D_;
    const float* Vg = g_v + ((size_t)b * KVH_ + kh) * (size_t)S_ * D_;

    const int tid  = threadIdx.x;
    const int w    = tid >> 5;
    const int lane = tid & 31;
    const int lane4 = lane >> 2;
    const int lanek = lane & 3;

    for (int e = tid; e < FBR * 32; e += 256) {
        int r = e >> 5, c = e & 31;
        *(float4*)&sQ[r * ADP + c * 4] = ((const float4*)Qg)[r * 32 + c];
    }

    float oacc[16][4];
#pragma unroll
    for (int nt = 0; nt < 16; nt++)
#pragma unroll
        for (int t = 0; t < 4; t++) oacc[nt][t] = 0.f;
    float m0 = -1e30f, m1 = -1e30f, l0 = 0.f, l1 = 0.f;

    const uint32_t* sQu = (const uint32_t*)sQ;
    const uint32_t* sKu = (const uint32_t*)sK;
    const uint32_t* sVu = (const uint32_t*)sV;
    uint32_t* sPw = (uint32_t*)sP + w * (16 * APP);

    for (int t0 = 0; t0 < S_; t0 += 64) {
        __syncthreads();
        for (int e = tid; e < 64 * 32; e += 256) {
            int r = e >> 5, c = e & 31;
            *(float4*)&sK[r * ADP + c * 4] = ((const float4*)(Kg + (size_t)t0 * D_))[r * 32 + c];
            *(float4*)&sV[r * ADP + c * 4] = ((const float4*)(Vg + (size_t)t0 * D_))[r * 32 + c];
        }
        __syncthreads();

        float sc[8][4];
#pragma unroll
        for (int nt = 0; nt < 8; nt++)
#pragma unroll
            for (int t = 0; t < 4; t++) sc[nt][t] = 0.f;

#pragma unroll
        for (int kk = 0; kk < 16; kk++) {
            uint32_t a[4];
            const uint32_t* qp = sQu + (w * 16 + lane4) * ADP + kk * 8 + lanek;
            a[0] = qp[0]; a[1] = qp[8 * ADP]; a[2] = qp[4]; a[3] = qp[8 * ADP + 4];
#pragma unroll
            for (int nt = 0; nt < 8; nt++) {
                uint32_t bb[2];
                const uint32_t* kp = sKu + (nt * 8 + lane4) * ADP + kk * 8 + lanek;
                bb[0] = kp[0]; bb[1] = kp[4];
                mma_tf32(sc[nt], a, bb);
            }
        }

        float mx0 = -1e30f, mx1 = -1e30f;
#pragma unroll
        for (int nt = 0; nt < 8; nt++) {
            mx0 = fmaxf(mx0, fmaxf(sc[nt][0], sc[nt][1]));
            mx1 = fmaxf(mx1, fmaxf(sc[nt][2], sc[nt][3]));
        }
        mx0 = fmaxf(mx0, __shfl_xor_sync(0xffffffffu, mx0, 1));
        mx0 = fmaxf(mx0, __shfl_xor_sync(0xffffffffu, mx0, 2));
        mx1 = fmaxf(mx1, __shfl_xor_sync(0xffffffffu, mx1, 1));
        mx1 = fmaxf(mx1, __shfl_xor_sync(0xffffffffu, mx1, 2));
        float mn0 = fmaxf(m0, mx0), mn1 = fmaxf(m1, mx1);
        float cr0 = ex2f(m0 - mn0), cr1 = ex2f(m1 - mn1);

        float s0 = 0.f, s1 = 0.f;
#pragma unroll
        for (int nt = 0; nt < 8; nt++) {
            float p00 = ex2f(sc[nt][0] - mn0);
            float p01 = ex2f(sc[nt][1] - mn0);
            float p10 = ex2f(sc[nt][2] - mn1);
            float p11 = ex2f(sc[nt][3] - mn1);
            s0 += p00 + p01;
            s1 += p10 + p11;
            *(uint2*)&sPw[lane4 * APP + nt * 8 + 2 * lanek] =
                make_uint2(f2tf32(p00), f2tf32(p01));
            *(uint2*)&sPw[(lane4 + 8) * APP + nt * 8 + 2 * lanek] =
                make_uint2(f2tf32(p10), f2tf32(p11));
        }
        s0 += __shfl_xor_sync(0xffffffffu, s0, 1);
        s0 += __shfl_xor_sync(0xffffffffu, s0, 2);
        s1 += __shfl_xor_sync(0xffffffffu, s1, 1);
        s1 += __shfl_xor_sync(0xffffffffu, s1, 2);
        l0 = l0 * cr0 + s0;
        l1 = l1 * cr1 + s1;
        m0 = mn0; m1 = mn1;

#pragma unroll
        for (int nt = 0; nt < 16; nt++) {
            oacc[nt][0] *= cr0; oacc[nt][1] *= cr0;
            oacc[nt][2] *= cr1; oacc[nt][3] *= cr1;
        }
        __syncwarp();

#pragma unroll
        for (int kk = 0; kk < 8; kk++) {
            uint32_t a[4];
            const uint32_t* pp = sPw + lane4 * APP + kk * 8 + lanek;
            a[0] = pp[0]; a[1] = pp[8 * APP]; a[2] = pp[4]; a[3] = pp[8 * APP + 4];
#pragma unroll
            for (int nt = 0; nt < 16; nt++) {
                uint32_t bb[2];
                const uint32_t* vp = sVu + (kk * 8 + lanek) * ADP + nt * 8 + lane4;
                bb[0] = vp[0]; bb[1] = vp[4 * ADP];
                mma_tf32(oacc[nt], a, bb);
            }
        }
        __syncwarp();
    }

    float i0 = 1.f / l0, i1 = 1.f / l1;
    int row0 = q0 + w * 16 + lane4;
    uint32_t* O0 = (uint32_t*)AO + ((size_t)(b * S_ + row0) * H_ + h) * D_;
    uint32_t* O1 = O0 + (size_t)8 * H_ * D_;
#pragma unroll
    for (int nt = 0; nt < 16; nt++) {
        int col = nt * 8 + 2 * lanek;
        *(uint2*)&O0[col] = make_uint2(f2tf32(oacc[nt][0] * i0), f2tf32(oacc[nt][1] * i0));
        *(uint2*)&O1[col] = make_uint2(f2tf32(oacc[nt][2] * i1), f2tf32(oacc[nt][3] * i1));
    }
}

// ---------------------------------------------------------------------------
extern "C" void kernel_launch(void* const* d_in, const int* in_sizes, int n_in,
                              void* d_out, int out_size)
{
    const float* hidden = (const float*)d_in[0];
    const float* cosb   = (const float*)d_in[1];
    const float* sinb   = (const float*)d_in[2];
    const float* qkv_w  = (const float*)d_in[3];
    const float* o_w    = (const float*)d_in[4];
    const float* qnw    = (const float*)d_in[5];
    const float* knw    = (const float*)d_in[6];
    float* out = (float*)d_out;

    float *qkvp, *aop, *htp, *w1p, *w2p;
    cudaGetSymbolAddress((void**)&qkvp, g_qkv);
    cudaGetSymbolAddress((void**)&aop,  g_ao);
    cudaGetSymbolAddress((void**)&htp,  g_ht);
    cudaGetSymbolAddress((void**)&w1p,  g_w1);
    cudaGetSymbolAddress((void**)&w2p,  g_w2);

    cudaFuncSetAttribute(gemm_mma, cudaFuncAttributeMaxDynamicSharedMemorySize,
                         G_DYN_SMEM);
    cudaFuncSetAttribute(flash_attn_mma, cudaFuncAttributeMaxDynamicSharedMemorySize,
                         ATTN_SMEM);

    // 0) One-time tf32 pre-convert of GEMM inputs
    int nh = MTOK * HID_ / 4, nw1 = QKVN * HID_ / 4, nw2 = HID_ * HID_ / 4;
    cvt_tf32<<<(nh  + 255) / 256, 256>>>(hidden, htp, nh);
    cvt_tf32<<<(nw1 + 255) / 256, 256>>>(qkv_w,  w1p, nw1);
    cvt_tf32<<<(nw2 + 255) / 256, 256>>>(o_w,    w2p, nw2);

    // 1) QKV projection (128x128 CTA, 64x32 warp tile, 3 CTAs/SM)
    dim3 g1(QKVN / GBN, MTOK / GBM);
    gemm_mma<<<g1, 256, G_DYN_SMEM>>>(htp, w1p, qkvp, MTOK, QKVN, HID_);

    // 2) RoPE + RMSNorm + scatter (one block per token)
    rope_norm<<<MTOK, 128>>>(cosb, sinb, qnw, knw);

    // 3) Attention (tf32 mma.sync flash, BR=128, 8 warps — R9 version)
    dim3 g3(S_ / FBR, H_, B_);
    flash_attn_mma<<<g3, 256, ATTN_SMEM>>>(aop);

    // 4) O projection
    dim3 g4(HID_ / GBN, MTOK / GBM);
    gemm_mma<<<g4, 256, G_DYN_SMEM>>>(aop, w2p, out, MTOK, HID_, H_ * D_);
}

// round 12
// speedup vs baseline: 1.4625x; 1.3080x over previous
#include <cuda_runtime.h>
#include <cstdint>
#include <math.h>

// Problem constants
#define B_    2
#define S_    2048
#define HID_  4096
#define H_    32
#define KVH_  8
#define D_    128
#define NREP  (H_/KVH_)                 // 4
#define QKVN  (HID_ + 2*KVH_*D_)        // 6144
#define MTOK  (B_*S_)                   // 4096

// Scratch (static device globals; no runtime allocation allowed)
__device__ float g_qkv[(size_t)MTOK * QKVN];            // [tok][6144] fp32
__device__ float g_q  [(size_t)B_*H_*S_*D_];            // tf32 bits, pre-scaled
__device__ float g_k  [(size_t)B_*KVH_*S_*D_];          // tf32 bits
__device__ float g_v  [(size_t)B_*KVH_*S_*D_];          // tf32 bits
__device__ float g_ao [(size_t)MTOK * H_*D_];           // tf32 bits
__device__ float g_ht [(size_t)MTOK * HID_];            // hidden, tf32 bits
__device__ float g_w1 [(size_t)QKVN * HID_];            // qkv_w, tf32 bits
__device__ float g_w2 [(size_t)HID_ * HID_];            // o_w, tf32 bits

__device__ __forceinline__ uint32_t f2tf32(float f) {
    uint32_t r;
    asm("cvt.rna.tf32.f32 %0, %1;" : "=r"(r) : "f"(f));
    return r;
}
__device__ __forceinline__ float ex2f(float x) {
    float y;
    asm("ex2.approx.f32 %0, %1;" : "=f"(y) : "f"(x));
    return y;
}
__device__ __forceinline__ void mma_tf32(float* c, const uint32_t* a, const uint32_t* b) {
    asm volatile(
        "mma.sync.aligned.m16n8k8.row.col.f32.tf32.tf32.f32 "
        "{%0,%1,%2,%3}, {%4,%5,%6,%7}, {%8,%9}, {%0,%1,%2,%3};"
        : "+f"(c[0]), "+f"(c[1]), "+f"(c[2]), "+f"(c[3])
        : "r"(a[0]), "r"(a[1]), "r"(a[2]), "r"(a[3]), "r"(b[0]), "r"(b[1]));
}
__device__ __forceinline__ void cp_async16(uint32_t saddr, const void* gaddr) {
    asm volatile("cp.async.cg.shared.global [%0], [%1], 16;"
                 :: "r"(saddr), "l"(gaddr) : "memory");
}

// ---------------------------------------------------------------------------
// One-time tf32 pre-convert (elementwise, vectorized)
// ---------------------------------------------------------------------------
__global__ __launch_bounds__(256) void cvt_tf32(
    const float* __restrict__ in, float* __restrict__ out, int n4)
{
    int i = blockIdx.x * 256 + threadIdx.x;
    if (i >= n4) return;
    float4 v = ((const float4*)in)[i];
    uint4 u;
    u.x = f2tf32(v.x); u.y = f2tf32(v.y); u.z = f2tf32(v.z); u.w = f2tf32(v.w);
    ((uint4*)out)[i] = u;
}

// ===========================================================================
// tf32 mma.sync GEMM (NT): C = A * B^T, inputs pre-rounded tf32 bits.
// EXACT R4 structure (best measured: tensor 43%, issue 37.6%, L1 89.5%):
// 128x128 CTA, 8 warps (2x4), 64x32 warp tile, BK=16, 3-stage cp.async,
// two barriers per iter, prefetch AFTER compute, full register freedom,
// af/bf fragments loaded up-front per k-substep. Only change vs R4: raw
// uint loads (inputs pre-converted) instead of in-loop cvt.
// ===========================================================================
#define GBM 128
#define GBN 128
#define GBK 16
#define GSTRIDE 20
#define G_TILE_FLOATS (128 * GSTRIDE)     // 2560 floats = 10240 B
#define G_STAGE_FLOATS (2 * G_TILE_FLOATS)
#define G_NSTAGE 3
#define G_DYN_SMEM (G_NSTAGE * G_STAGE_FLOATS * 4)   // 61440 bytes

__global__ __launch_bounds__(256) void gemm_mma(
    const float* __restrict__ A, const float* __restrict__ Bm,
    float* __restrict__ C, int M, int N, int K)
{
    extern __shared__ float sdyn[];
    const uint32_t sbase = (uint32_t)__cvta_generic_to_shared(sdyn);

    const int tid  = threadIdx.x;
    const int wid  = tid >> 5;
    const int lane = tid & 31;
    const int warp_m = wid >> 2;
    const int warp_n = wid & 3;
    const int lane4 = lane >> 2;
    const int lanek = lane & 3;
    const int m0 = blockIdx.y * GBM;
    const int n0 = blockIdx.x * GBN;
    const int NK = K >> 4;

    const int r  = tid >> 1;
    const int c0 = (tid & 1) * 2;
    const float* Ag = A  + (size_t)(m0 + r) * K;
    const float* Bg = Bm + (size_t)(n0 + r) * K;
    const uint32_t sArow = sbase + (uint32_t)r * (GSTRIDE * 4);
    const uint32_t sBrow = sArow + G_TILE_FLOATS * 4;

    // Prologue: fill all 3 stages
#pragma unroll
    for (int s = 0; s < G_NSTAGE; s++) {
        uint32_t so = (uint32_t)s * (G_STAGE_FLOATS * 4);
        const float* ag = Ag + s * GBK;
        const float* bg = Bg + s * GBK;
        cp_async16(sArow + so + (c0    ) * 16, ag + (c0    ) * 4);
        cp_async16(sArow + so + (c0 + 1) * 16, ag + (c0 + 1) * 4);
        cp_async16(sBrow + so + (c0    ) * 16, bg + (c0    ) * 4);
        cp_async16(sBrow + so + (c0 + 1) * 16, bg + (c0 + 1) * 4);
        asm volatile("cp.async.commit_group;" ::: "memory");
    }

    float acc[4][4][4];
#pragma unroll
    for (int i = 0; i < 4; i++)
#pragma unroll
        for (int j = 0; j < 4; j++)
#pragma unroll
            for (int t = 0; t < 4; t++) acc[i][j][t] = 0.f;

    for (int it = 0; it < NK; it++) {
        asm volatile("cp.async.wait_group %0;" :: "n"(G_NSTAGE - 1) : "memory");
        __syncthreads();

        const uint32_t* sA = (const uint32_t*)(sdyn + (it % G_NSTAGE) * G_STAGE_FLOATS);
        const uint32_t* sB = sA + G_TILE_FLOATS;

#pragma unroll
        for (int ks = 0; ks < 2; ks++) {
            const int kb = ks * 8 + lanek;
            uint32_t af[4][4], bf[4][2];
#pragma unroll
            for (int mt = 0; mt < 4; mt++) {
                const uint32_t* ap = sA + (warp_m * 64 + mt * 16 + lane4) * GSTRIDE + kb;
                af[mt][0] = ap[0];
                af[mt][1] = ap[8 * GSTRIDE];
                af[mt][2] = ap[4];
                af[mt][3] = ap[8 * GSTRIDE + 4];
            }
#pragma unroll
            for (int nt = 0; nt < 4; nt++) {
                const uint32_t* bp = sB + (warp_n * 32 + nt * 8 + lane4) * GSTRIDE + kb;
                bf[nt][0] = bp[0];
                bf[nt][1] = bp[4];
            }
#pragma unroll
            for (int mt = 0; mt < 4; mt++)
#pragma unroll
                for (int nt = 0; nt < 4; nt++)
                    mma_tf32(acc[mt][nt], af[mt], bf[nt]);
        }

        __syncthreads();   // all warps done reading this stage

        int itn = it + G_NSTAGE;
        if (itn < NK) {
            uint32_t so = (uint32_t)(itn % G_NSTAGE) * (G_STAGE_FLOATS * 4);
            const float* ag = Ag + itn * GBK;
            const float* bg = Bg + itn * GBK;
            cp_async16(sArow + so + (c0    ) * 16, ag + (c0    ) * 4);
            cp_async16(sArow + so + (c0 + 1) * 16, ag + (c0 + 1) * 4);
            cp_async16(sBrow + so + (c0    ) * 16, bg + (c0    ) * 4);
            cp_async16(sBrow + so + (c0 + 1) * 16, bg + (c0 + 1) * 4);
        }
        asm volatile("cp.async.commit_group;" ::: "memory");
    }

#pragma unroll
    for (int mt = 0; mt < 4; mt++) {
#pragma unroll
        for (int nt = 0; nt < 4; nt++) {
            int row = m0 + warp_m * 64 + mt * 16 + lane4;
            int col = n0 + warp_n * 32 + nt * 8 + lanek * 2;
            *(float2*)&C[(size_t)row * N + col] =
                make_float2(acc[mt][nt][0], acc[mt][nt][1]);
            *(float2*)&C[(size_t)(row + 8) * N + col] =
                make_float2(acc[mt][nt][2], acc[mt][nt][3]);
        }
    }
}

// ---------------------------------------------------------------------------
// RoPE + per-head RMSNorm + scatter, one block per TOKEN (R9 version).
// ---------------------------------------------------------------------------
__global__ __launch_bounds__(128) void rope_norm(
    const float* __restrict__ cosb, const float* __restrict__ sinb,
    const float* __restrict__ qw,   const float* __restrict__ kw)
{
    const int tok = blockIdx.x;
    const int b = tok / S_, s = tok % S_;
    const int tid = threadIdx.x;
    const int w = tid >> 5, lane = tid & 31;
    const float QSC = 0.08838834764831845f * 1.4426950408889634f;

    const float* row = g_qkv + (size_t)tok * QKVN;
    float c4[4], s4[4], qw4[4], kw4[4];
#pragma unroll
    for (int j = 0; j < 4; j++) {
        int d = lane + 32 * j;
        c4[j]  = cosb[((size_t)b * S_ + s) * D_ + d];
        s4[j]  = sinb[((size_t)b * S_ + s) * D_ + d];
        qw4[j] = qw[d];
        kw4[j] = kw[d];
    }

    for (int hh = w; hh < H_ + KVH_; hh += 4) {
        int off = (hh < H_) ? hh * D_ : H_ * D_ + (hh - H_) * D_;
        float x[4], y[4];
#pragma unroll
        for (int j = 0; j < 4; j++) x[j] = row[off + lane + 32 * j];
        y[0] = x[0] * c4[0] - x[2] * s4[0];
        y[1] = x[1] * c4[1] - x[3] * s4[1];
        y[2] = x[2] * c4[2] + x[0] * s4[2];
        y[3] = x[3] * c4[3] + x[1] * s4[3];
        float v2 = y[0] * y[0] + y[1] * y[1] + y[2] * y[2] + y[3] * y[3];
#pragma unroll
        for (int o = 16; o; o >>= 1) v2 += __shfl_xor_sync(0xffffffffu, v2, o);
        float inv = rsqrtf(v2 * (1.f / D_) + 1e-6f);

        if (hh < H_) {
            uint32_t* dst = (uint32_t*)g_q + (((size_t)b * H_ + hh) * S_ + s) * D_;
#pragma unroll
            for (int j = 0; j < 4; j++)
                dst[lane + 32 * j] = f2tf32(qw4[j] * y[j] * inv * QSC);
        } else {
            uint32_t* dst = (uint32_t*)g_k +
                (((size_t)b * KVH_ + (hh - H_)) * S_ + s) * D_;
#pragma unroll
            for (int j = 0; j < 4; j++)
                dst[lane + 32 * j] = f2tf32(kw4[j] * y[j] * inv);
        }
    }

    for (int kv = w; kv < KVH_; kv += 4) {
        const float* src = row + H_ * D_ + KVH_ * D_ + kv * D_;
        uint32_t* dst = (uint32_t*)g_v + (((size_t)b * KVH_ + kv) * S_ + s) * D_;
#pragma unroll
        for (int j = 0; j < 4; j++)
            dst[lane + 32 * j] = f2tf32(src[lane + 32 * j]);
    }
}

// ---------------------------------------------------------------------------
// Flash attention with tf32 mma.sync (R9 version). BR=128 (8 warps, 256 thr),
// BC=64, D=128. Inputs pre-converted tf32 bits. Output tf32 bits -> g_ao.
// ---------------------------------------------------------------------------
#define FBR 128
#define ADP 132
#define APP 68
#define ATTN_SMEM ((FBR * ADP + 2 * 64 * ADP + 8 * 16 * APP) * 4)  // 169984 B

__global__ __launch_bounds__(256) void flash_attn_mma(float* __restrict__ AO)
{
    extern __shared__ float sm[];
    float* sQ = sm;                        // 128 x 132
    float* sK = sQ + FBR * ADP;            // 64 x 132
    float* sV = sK + 64 * ADP;             // 64 x 132
    float* sP = sV + 64 * ADP;             // 8 warps x 16 x 68

    const int b  = blockIdx.z, h = blockIdx.y;
    const int q0 = blockIdx.x * FBR;
    const int kh = h / NREP;
    const float* Qg = g_q + (((size_t)b * H_ + h) * S_ + q0) * D_;
    const float* Kg = g_k + ((size_t)b * KVH_ + kh) * (size_t)S_ * D_;
    const float* Vg = g_v + ((size_t)b * KVH_ + kh) * (size_t)S_ * D_;

    const int tid  = threadIdx.x;
    const int w    = tid >> 5;
    const int lane = tid & 31;
    const int lane4 = lane >> 2;
    const int lanek = lane & 3;

    for (int e = tid; e < FBR * 32; e += 256) {
        int r = e >> 5, c = e & 31;
        *(float4*)&sQ[r * ADP + c * 4] = ((const float4*)Qg)[r * 32 + c];
    }

    float oacc[16][4];
#pragma unroll
    for (int nt = 0; nt < 16; nt++)
#pragma unroll
        for (int t = 0; t < 4; t++) oacc[nt][t] = 0.f;
    float m0 = -1e30f, m1 = -1e30f, l0 = 0.f, l1 = 0.f;

    const uint32_t* sQu = (const uint32_t*)sQ;
    const uint32_t* sKu = (const uint32_t*)sK;
    const uint32_t* sVu = (const uint32_t*)sV;
    uint32_t* sPw = (uint32_t*)sP + w * (16 * APP);

    for (int t0 = 0; t0 < S_; t0 += 64) {
        __syncthreads();
        for (int e = tid; e < 64 * 32; e += 256) {
            int r = e >> 5, c = e & 31;
            *(float4*)&sK[r * ADP + c * 4] = ((const float4*)(Kg + (size_t)t0 * D_))[r * 32 + c];
            *(float4*)&sV[r * ADP + c * 4] = ((const float4*)(Vg + (size_t)t0 * D_))[r * 32 + c];
        }
        __syncthreads();

        float sc[8][4];
#pragma unroll
        for (int nt = 0; nt < 8; nt++)
#pragma unroll
            for (int t = 0; t < 4; t++) sc[nt][t] = 0.f;

#pragma unroll
        for (int kk = 0; kk < 16; kk++) {
            uint32_t a[4];
            const uint32_t* qp = sQu + (w * 16 + lane4) * ADP + kk * 8 + lanek;
            a[0] = qp[0]; a[1] = qp[8 * ADP]; a[2] = qp[4]; a[3] = qp[8 * ADP + 4];
#pragma unroll
            for (int nt = 0; nt < 8; nt++) {
                uint32_t bb[2];
                const uint32_t* kp = sKu + (nt * 8 + lane4) * ADP + kk * 8 + lanek;
                bb[0] = kp[0]; bb[1] = kp[4];
                mma_tf32(sc[nt], a, bb);
            }
        }

        float mx0 = -1e30f, mx1 = -1e30f;
#pragma unroll
        for (int nt = 0; nt < 8; nt++) {
            mx0 = fmaxf(mx0, fmaxf(sc[nt][0], sc[nt][1]));
            mx1 = fmaxf(mx1, fmaxf(sc[nt][2], sc[nt][3]));
        }
        mx0 = fmaxf(mx0, __shfl_xor_sync(0xffffffffu, mx0, 1));
        mx0 = fmaxf(mx0, __shfl_xor_sync(0xffffffffu, mx0, 2));
        mx1 = fmaxf(mx1, __shfl_xor_sync(0xffffffffu, mx1, 1));
        mx1 = fmaxf(mx1, __shfl_xor_sync(0xffffffffu, mx1, 2));
        float mn0 = fmaxf(m0, mx0), mn1 = fmaxf(m1, mx1);
        float cr0 = ex2f(m0 - mn0), cr1 = ex2f(m1 - mn1);

        float s0 = 0.f, s1 = 0.f;
#pragma unroll
        for (int nt = 0; nt < 8; nt++) {
            float p00 = ex2f(sc[nt][0] - mn0);
            float p01 = ex2f(sc[nt][1] - mn0);
            float p10 = ex2f(sc[nt][2] - mn1);
            float p11 = ex2f(sc[nt][3] - mn1);
            s0 += p00 + p01;
            s1 += p10 + p11;
            *(uint2*)&sPw[lane4 * APP + nt * 8 + 2 * lanek] =
                make_uint2(f2tf32(p00), f2tf32(p01));
            *(uint2*)&sPw[(lane4 + 8) * APP + nt * 8 + 2 * lanek] =
                make_uint2(f2tf32(p10), f2tf32(p11));
        }
        s0 += __shfl_xor_sync(0xffffffffu, s0, 1);
        s0 += __shfl_xor_sync(0xffffffffu, s0, 2);
        s1 += __shfl_xor_sync(0xffffffffu, s1, 1);
        s1 += __shfl_xor_sync(0xffffffffu, s1, 2);
        l0 = l0 * cr0 + s0;
        l1 = l1 * cr1 + s1;
        m0 = mn0; m1 = mn1;

#pragma unroll
        for (int nt = 0; nt < 16; nt++) {
            oacc[nt][0] *= cr0; oacc[nt][1] *= cr0;
            oacc[nt][2] *= cr1; oacc[nt][3] *= cr1;
        }
        __syncwarp();

#pragma unroll
        for (int kk = 0; kk < 8; kk++) {
            uint32_t a[4];
            const uint32_t* pp = sPw + lane4 * APP + kk * 8 + lanek;
            a[0] = pp[0]; a[1] = pp[8 * APP]; a[2] = pp[4]; a[3] = pp[8 * APP + 4];
#pragma unroll
            for (int nt = 0; nt < 16; nt++) {
                uint32_t bb[2];
                const uint32_t* vp = sVu + (kk * 8 + lanek) * ADP + nt * 8 + lane4;
                bb[0] = vp[0]; bb[1] = vp[4 * ADP];
                mma_tf32(oacc[nt], a, bb);
            }
        }
        __syncwarp();
    }

    float i0 = 1.f / l0, i1 = 1.f / l1;
    int row0 = q0 + w * 16 + lane4;
    uint32_t* O0 = (uint32_t*)AO + ((size_t)(b * S_ + row0) * H_ + h) * D_;
    uint32_t* O1 = O0 + (size_t)8 * H_ * D_;
#pragma unroll
    for (int nt = 0; nt < 16; nt++) {
        int col = nt * 8 + 2 * lanek;
        *(uint2*)&O0[col] = make_uint2(f2tf32(oacc[nt][0] * i0), f2tf32(oacc[nt][1] * i0));
        *(uint2*)&O1[col] = make_uint2(f2tf32(oacc[nt][2] * i1), f2tf32(oacc[nt][3] * i1));
    }
}

// ---------------------------------------------------------------------------
extern "C" void kernel_launch(void* const* d_in, const int* in_sizes, int n_in,
                              void* d_out, int out_size)
{
    const float* hidden = (const float*)d_in[0];
    const float* cosb   = (const float*)d_in[1];
    const float* sinb   = (const float*)d_in[2];
    const float* qkv_w  = (const float*)d_in[3];
    const float* o_w    = (const float*)d_in[4];
    const float* qnw    = (const float*)d_in[5];
    const float* knw    = (const float*)d_in[6];
    float* out = (float*)d_out;

    float *qkvp, *aop, *htp, *w1p, *w2p;
    cudaGetSymbolAddress((void**)&qkvp, g_qkv);
    cudaGetSymbolAddress((void**)&aop,  g_ao);
    cudaGetSymbolAddress((void**)&htp,  g_ht);
    cudaGetSymbolAddress((void**)&w1p,  g_w1);
    cudaGetSymbolAddress((void**)&w2p,  g_w2);

    cudaFuncSetAttribute(gemm_mma, cudaFuncAttributeMaxDynamicSharedMemorySize,
                         G_DYN_SMEM);
    cudaFuncSetAttribute(flash_attn_mma, cudaFuncAttributeMaxDynamicSharedMemorySize,
                         ATTN_SMEM);

    // 0) One-time tf32 pre-convert of GEMM inputs
    int nh = MTOK * HID_ / 4, nw1 = QKVN * HID_ / 4, nw2 = HID_ * HID_ / 4;
    cvt_tf32<<<(nh  + 255) / 256, 256>>>(hidden, htp, nh);
    cvt_tf32<<<(nw1 + 255) / 256, 256>>>(qkv_w,  w1p, nw1);
    cvt_tf32<<<(nw2 + 255) / 256, 256>>>(o_w,    w2p, nw2);

    // 1) QKV projection (R4-structure gemm)
    dim3 g1(QKVN / GBN, MTOK / GBM);
    gemm_mma<<<g1, 256, G_DYN_SMEM>>>(htp, w1p, qkvp, MTOK, QKVN, HID_);

    // 2) RoPE + RMSNorm + scatter (one block per token)
    rope_norm<<<MTOK, 128>>>(cosb, sinb, qnw, knw);

    // 3) Attention (tf32 mma.sync flash, BR=128, 8 warps)
    dim3 g3(S_ / FBR, H_, B_);
    flash_attn_mma<<<g3, 256, ATTN_SMEM>>>(aop);

    // 4) O projection
    dim3 g4(HID_ / GBN, MTOK / GBM);
    gemm_mma<<<g4, 256, G_DYN_SMEM>>>(aop, w2p, out, MTOK, HID_, H_ * D_);
}

// round 13
// speedup vs baseline: 2.1597x; 1.4767x over previous
#include <cuda_runtime.h>
#include <cuda_fp16.h>
#include <cstdint>
#include <math.h>

// Problem constants
#define B_    2
#define S_    2048
#define HID_  4096
#define H_    32
#define KVH_  8
#define D_    128
#define NREP  (H_/KVH_)                 // 4
#define QKVN  (HID_ + 2*KVH_*D_)        // 6144
#define MTOK  (B_*S_)                   // 4096

// Scratch (static device globals; no runtime allocation allowed)
__device__ float  g_qkv[(size_t)MTOK * QKVN];           // [tok][6144] fp32
__device__ float  g_q  [(size_t)B_*H_*S_*D_];           // tf32 bits, pre-scaled
__device__ float  g_k  [(size_t)B_*KVH_*S_*D_];         // tf32 bits
__device__ float  g_v  [(size_t)B_*KVH_*S_*D_];         // tf32 bits
__device__ __half g_ao [(size_t)MTOK * H_*D_];          // fp16 (O-GEMM input)
__device__ __half g_ht [(size_t)MTOK * HID_];           // hidden, fp16
__device__ __half g_w1 [(size_t)QKVN * HID_];           // qkv_w, fp16
__device__ __half g_w2 [(size_t)HID_ * HID_];           // o_w, fp16

__device__ __forceinline__ uint32_t f2tf32(float f) {
    uint32_t r;
    asm("cvt.rna.tf32.f32 %0, %1;" : "=r"(r) : "f"(f));
    return r;
}
__device__ __forceinline__ float ex2f(float x) {
    float y;
    asm("ex2.approx.f32 %0, %1;" : "=f"(y) : "f"(x));
    return y;
}
__device__ __forceinline__ void mma_tf32(float* c, const uint32_t* a, const uint32_t* b) {
    asm volatile(
        "mma.sync.aligned.m16n8k8.row.col.f32.tf32.tf32.f32 "
        "{%0,%1,%2,%3}, {%4,%5,%6,%7}, {%8,%9}, {%0,%1,%2,%3};"
        : "+f"(c[0]), "+f"(c[1]), "+f"(c[2]), "+f"(c[3])
        : "r"(a[0]), "r"(a[1]), "r"(a[2]), "r"(a[3]), "r"(b[0]), "r"(b[1]));
}
__device__ __forceinline__ void mma_f16(float* c, const uint32_t* a, const uint32_t* b) {
    asm volatile(
        "mma.sync.aligned.m16n8k16.row.col.f32.f16.f16.f32 "
        "{%0,%1,%2,%3}, {%4,%5,%6,%7}, {%8,%9}, {%0,%1,%2,%3};"
        : "+f"(c[0]), "+f"(c[1]), "+f"(c[2]), "+f"(c[3])
        : "r"(a[0]), "r"(a[1]), "r"(a[2]), "r"(a[3]), "r"(b[0]), "r"(b[1]));
}
__device__ __forceinline__ void cp_async16(uint32_t saddr, const void* gaddr) {
    asm volatile("cp.async.cg.shared.global [%0], [%1], 16;"
                 :: "r"(saddr), "l"(gaddr) : "memory");
}

// ---------------------------------------------------------------------------
// One-time fp16 pre-convert of GEMM inputs (vectorized)
// ---------------------------------------------------------------------------
__global__ __launch_bounds__(256) void cvt_f16(
    const float* __restrict__ in, __half* __restrict__ out, int n4)
{
    int i = blockIdx.x * 256 + threadIdx.x;
    if (i >= n4) return;
    float4 v = ((const float4*)in)[i];
    __half2 h01 = __floats2half2_rn(v.x, v.y);
    __half2 h23 = __floats2half2_rn(v.z, v.w);
    uint2 u;
    u.x = *(uint32_t*)&h01;
    u.y = *(uint32_t*)&h23;
    ((uint2*)out)[i] = u;
}

// ===========================================================================
// fp16 mma.sync GEMM (NT): C[M,N] = A[M,K] * B[N,K]^T, fp16 in, fp32 out.
// R12 (best) structure: 128x128 CTA, 8 warps (2x4), 64x32 warp tile,
// 3-stage cp.async, two barriers per iter. BK=32 (one m16n8k16 pair per
// substep): HALF the barriers / crossbar bytes / MMA instrs of the tf32
// version at identical FLOPs. Row = 32 halfs + 8 pad = 20 uint32 (80B):
// bank(row,lanek) = (20*row + lanek) % 32 -> all 32 distinct (verified).
// ===========================================================================
#define GBM 128
#define GBN 128
#define GBK 32
#define GSTRIDE 20                         // uint32 per row (40 halfs)
#define G_TILE_U32 (128 * GSTRIDE)         // 2560 uint32 = 10240 B
#define G_STAGE_U32 (2 * G_TILE_U32)
#define G_NSTAGE 3
#define G_DYN_SMEM (G_NSTAGE * G_STAGE_U32 * 4)   // 61440 bytes

__global__ __launch_bounds__(256) void gemm_f16(
    const __half* __restrict__ A, const __half* __restrict__ Bm,
    float* __restrict__ C, int M, int N, int K)
{
    extern __shared__ uint32_t sdyn[];
    const uint32_t sbase = (uint32_t)__cvta_generic_to_shared(sdyn);

    const int tid  = threadIdx.x;
    const int wid  = tid >> 5;
    const int lane = tid & 31;
    const int warp_m = wid >> 2;
    const int warp_n = wid & 3;
    const int lane4 = lane >> 2;
    const int lanek = lane & 3;
    const int m0 = blockIdx.y * GBM;
    const int n0 = blockIdx.x * GBN;
    const int NK = K >> 5;                 // BK=32 tiles

    // Loader: row r = tid/2, two 16B chunks (of 4) per operand per thread
    const int r  = tid >> 1;
    const int c0 = (tid & 1) * 2;
    const __half* Ag = A  + (size_t)(m0 + r) * K;
    const __half* Bg = Bm + (size_t)(n0 + r) * K;
    const uint32_t sArow = sbase + (uint32_t)r * (GSTRIDE * 4);
    const uint32_t sBrow = sArow + G_TILE_U32 * 4;

    // Prologue: fill all 3 stages
#pragma unroll
    for (int s = 0; s < G_NSTAGE; s++) {
        uint32_t so = (uint32_t)s * (G_STAGE_U32 * 4);
        const __half* ag = Ag + s * GBK;
        const __half* bg = Bg + s * GBK;
        cp_async16(sArow + so + (c0    ) * 16, ag + (c0    ) * 8);
        cp_async16(sArow + so + (c0 + 1) * 16, ag + (c0 + 1) * 8);
        cp_async16(sBrow + so + (c0    ) * 16, bg + (c0    ) * 8);
        cp_async16(sBrow + so + (c0 + 1) * 16, bg + (c0 + 1) * 8);
        asm volatile("cp.async.commit_group;" ::: "memory");
    }

    float acc[4][4][4];
#pragma unroll
    for (int i = 0; i < 4; i++)
#pragma unroll
        for (int j = 0; j < 4; j++)
#pragma unroll
            for (int t = 0; t < 4; t++) acc[i][j][t] = 0.f;

    for (int it = 0; it < NK; it++) {
        asm volatile("cp.async.wait_group %0;" :: "n"(G_NSTAGE - 1) : "memory");
        __syncthreads();

        const uint32_t* sA = sdyn + (it % G_NSTAGE) * G_STAGE_U32;
        const uint32_t* sB = sA + G_TILE_U32;

#pragma unroll
        for (int ks = 0; ks < 2; ks++) {
            const int kb = ks * 8 + lanek;   // uint32 offset (16 halfs per ks)
            uint32_t af[4][4], bf[4][2];
#pragma unroll
            for (int mt = 0; mt < 4; mt++) {
                const uint32_t* ap = sA + (warp_m * 64 + mt * 16 + lane4) * GSTRIDE + kb;
                af[mt][0] = ap[0];               // (row,   k0..k0+1)
                af[mt][1] = ap[8 * GSTRIDE];     // (row+8, k0..k0+1)
                af[mt][2] = ap[4];               // (row,   k0+8..k0+9)
                af[mt][3] = ap[8 * GSTRIDE + 4]; // (row+8, k0+8..k0+9)
            }
#pragma unroll
            for (int nt = 0; nt < 4; nt++) {
                const uint32_t* bp = sB + (warp_n * 32 + nt * 8 + lane4) * GSTRIDE + kb;
                bf[nt][0] = bp[0];
                bf[nt][1] = bp[4];
            }
#pragma unroll
            for (int mt = 0; mt < 4; mt++)
#pragma unroll
                for (int nt = 0; nt < 4; nt++)
                    mma_f16(acc[mt][nt], af[mt], bf[nt]);
        }

        __syncthreads();

        int itn = it + G_NSTAGE;
        if (itn < NK) {
            uint32_t so = (uint32_t)(itn % G_NSTAGE) * (G_STAGE_U32 * 4);
            const __half* ag = Ag + itn * GBK;
            const __half* bg = Bg + itn * GBK;
            cp_async16(sArow + so + (c0    ) * 16, ag + (c0    ) * 8);
            cp_async16(sArow + so + (c0 + 1) * 16, ag + (c0 + 1) * 8);
            cp_async16(sBrow + so + (c0    ) * 16, bg + (c0    ) * 8);
            cp_async16(sBrow + so + (c0 + 1) * 16, bg + (c0 + 1) * 8);
        }
        asm volatile("cp.async.commit_group;" ::: "memory");
    }

#pragma unroll
    for (int mt = 0; mt < 4; mt++) {
#pragma unroll
        for (int nt = 0; nt < 4; nt++) {
            int row = m0 + warp_m * 64 + mt * 16 + lane4;
            int col = n0 + warp_n * 32 + nt * 8 + lanek * 2;
            *(float2*)&C[(size_t)row * N + col] =
                make_float2(acc[mt][nt][0], acc[mt][nt][1]);
            *(float2*)&C[(size_t)(row + 8) * N + col] =
                make_float2(acc[mt][nt][2], acc[mt][nt][3]);
        }
    }
}

// ---------------------------------------------------------------------------
// RoPE + per-head RMSNorm + scatter, one block per TOKEN (R9/R12 version).
// Writes tf32 bits for attention (Q pre-scaled by scale*log2e).
// ---------------------------------------------------------------------------
__global__ __launch_bounds__(128) void rope_norm(
    const float* __restrict__ cosb, const float* __restrict__ sinb,
    const float* __restrict__ qw,   const float* __restrict__ kw)
{
    const int tok = blockIdx.x;
    const int b = tok / S_, s = tok % S_;
    const int tid = threadIdx.x;
    const int w = tid >> 5, lane = tid & 31;
    const float QSC = 0.08838834764831845f * 1.4426950408889634f;

    const float* row = g_qkv + (size_t)tok * QKVN;
    float c4[4], s4[4], qw4[4], kw4[4];
#pragma unroll
    for (int j = 0; j < 4; j++) {
        int d = lane + 32 * j;
        c4[j]  = cosb[((size_t)b * S_ + s) * D_ + d];
        s4[j]  = sinb[((size_t)b * S_ + s) * D_ + d];
        qw4[j] = qw[d];
        kw4[j] = kw[d];
    }

    for (int hh = w; hh < H_ + KVH_; hh += 4) {
        int off = (hh < H_) ? hh * D_ : H_ * D_ + (hh - H_) * D_;
        float x[4], y[4];
#pragma unroll
        for (int j = 0; j < 4; j++) x[j] = row[off + lane + 32 * j];
        y[0] = x[0] * c4[0] - x[2] * s4[0];
        y[1] = x[1] * c4[1] - x[3] * s4[1];
        y[2] = x[2] * c4[2] + x[0] * s4[2];
        y[3] = x[3] * c4[3] + x[1] * s4[3];
        float v2 = y[0] * y[0] + y[1] * y[1] + y[2] * y[2] + y[3] * y[3];
#pragma unroll
        for (int o = 16; o; o >>= 1) v2 += __shfl_xor_sync(0xffffffffu, v2, o);
        float inv = rsqrtf(v2 * (1.f / D_) + 1e-6f);

        if (hh < H_) {
            uint32_t* dst = (uint32_t*)g_q + (((size_t)b * H_ + hh) * S_ + s) * D_;
#pragma unroll
            for (int j = 0; j < 4; j++)
                dst[lane + 32 * j] = f2tf32(qw4[j] * y[j] * inv * QSC);
        } else {
            uint32_t* dst = (uint32_t*)g_k +
                (((size_t)b * KVH_ + (hh - H_)) * S_ + s) * D_;
#pragma unroll
            for (int j = 0; j < 4; j++)
                dst[lane + 32 * j] = f2tf32(kw4[j] * y[j] * inv);
        }
    }

    for (int kv = w; kv < KVH_; kv += 4) {
        const float* src = row + H_ * D_ + KVH_ * D_ + kv * D_;
        uint32_t* dst = (uint32_t*)g_v + (((size_t)b * KVH_ + kv) * S_ + s) * D_;
#pragma unroll
        for (int j = 0; j < 4; j++)
            dst[lane + 32 * j] = f2tf32(src[lane + 32 * j]);
    }
}

// ---------------------------------------------------------------------------
// Flash attention with tf32 mma.sync (R12 version). BR=128 (8 warps),
// BC=64, D=128. Inputs tf32 bits. Output: fp16 into g_ao for the O-GEMM.
// ---------------------------------------------------------------------------
#define FBR 128
#define ADP 132
#define APP 68
#define ATTN_SMEM ((FBR * ADP + 2 * 64 * ADP + 8 * 16 * APP) * 4)  // 169984 B

__global__ __launch_bounds__(256) void flash_attn_mma(__half* __restrict__ AO)
{
    extern __shared__ float sm[];
    float* sQ = sm;                        // 128 x 132
    float* sK = sQ + FBR * ADP;            // 64 x 132
    float* sV = sK + 64 * ADP;             // 64 x 132
    float* sP = sV + 64 * ADP;             // 8 warps x 16 x 68

    const int b  = blockIdx.z, h = blockIdx.y;
    const int q0 = blockIdx.x * FBR;
    const int kh = h / NREP;
    const float* Qg = g_q + (((size_t)b * H_ + h) * S_ + q0) * D_;
    const float* Kg = g_k + ((size_t)b * KVH_ + kh) * (size_t)S_ * D_;
    const float* Vg = g_v + ((size_t)b * KVH_ + kh) * (size_t)S_ * D_;

    const int tid  = threadIdx.x;
    const int w    = tid >> 5;
    const int lane = tid & 31;
    const int lane4 = lane >> 2;
    const int lanek = lane & 3;

    for (int e = tid; e < FBR * 32; e += 256) {
        int r = e >> 5, c = e & 31;
        *(float4*)&sQ[r * ADP + c * 4] = ((const float4*)Qg)[r * 32 + c];
    }

    float oacc[16][4];
#pragma unroll
    for (int nt = 0; nt < 16; nt++)
#pragma unroll
        for (int t = 0; t < 4; t++) oacc[nt][t] = 0.f;
    float m0 = -1e30f, m1 = -1e30f, l0 = 0.f, l1 = 0.f;

    const uint32_t* sQu = (const uint32_t*)sQ;
    const uint32_t* sKu = (const uint32_t*)sK;
    const uint32_t* sVu = (const uint32_t*)sV;
    uint32_t* sPw = (uint32_t*)sP + w * (16 * APP);

    for (int t0 = 0; t0 < S_; t0 += 64) {
        __syncthreads();
        for (int e = tid; e < 64 * 32; e += 256) {
            int r = e >> 5, c = e & 31;
            *(float4*)&sK[r * ADP + c * 4] = ((const float4*)(Kg + (size_t)t0 * D_))[r * 32 + c];
            *(float4*)&sV[r * ADP + c * 4] = ((const float4*)(Vg + (size_t)t0 * D_))[r * 32 + c];
        }
        __syncthreads();

        float sc[8][4];
#pragma unroll
        for (int nt = 0; nt < 8; nt++)
#pragma unroll
            for (int t = 0; t < 4; t++) sc[nt][t] = 0.f;

#pragma unroll
        for (int kk = 0; kk < 16; kk++) {
            uint32_t a[4];
            const uint32_t* qp = sQu + (w * 16 + lane4) * ADP + kk * 8 + lanek;
            a[0] = qp[0]; a[1] = qp[8 * ADP]; a[2] = qp[4]; a[3] = qp[8 * ADP + 4];
#pragma unroll
            for (int nt = 0; nt < 8; nt++) {
                uint32_t bb[2];
                const uint32_t* kp = sKu + (nt * 8 + lane4) * ADP + kk * 8 + lanek;
                bb[0] = kp[0]; bb[1] = kp[4];
                mma_tf32(sc[nt], a, bb);
            }
        }

        float mx0 = -1e30f, mx1 = -1e30f;
#pragma unroll
        for (int nt = 0; nt < 8; nt++) {
            mx0 = fmaxf(mx0, fmaxf(sc[nt][0], sc[nt][1]));
            mx1 = fmaxf(mx1, fmaxf(sc[nt][2], sc[nt][3]));
        }
        mx0 = fmaxf(mx0, __shfl_xor_sync(0xffffffffu, mx0, 1));
        mx0 = fmaxf(mx0, __shfl_xor_sync(0xffffffffu, mx0, 2));
        mx1 = fmaxf(mx1, __shfl_xor_sync(0xffffffffu, mx1, 1));
        mx1 = fmaxf(mx1, __shfl_xor_sync(0xffffffffu, mx1, 2));
        float mn0 = fmaxf(m0, mx0), mn1 = fmaxf(m1, mx1);
        float cr0 = ex2f(m0 - mn0), cr1 = ex2f(m1 - mn1);

        float s0 = 0.f, s1 = 0.f;
#pragma unroll
        for (int nt = 0; nt < 8; nt++) {
            float p00 = ex2f(sc[nt][0] - mn0);
            float p01 = ex2f(sc[nt][1] - mn0);
            float p10 = ex2f(sc[nt][2] - mn1);
            float p11 = ex2f(sc[nt][3] - mn1);
            s0 += p00 + p01;
            s1 += p10 + p11;
            *(uint2*)&sPw[lane4 * APP + nt * 8 + 2 * lanek] =
                make_uint2(f2tf32(p00), f2tf32(p01));
            *(uint2*)&sPw[(lane4 + 8) * APP + nt * 8 + 2 * lanek] =
                make_uint2(f2tf32(p10), f2tf32(p11));
        }
        s0 += __shfl_xor_sync(0xffffffffu, s0, 1);
        s0 += __shfl_xor_sync(0xffffffffu, s0, 2);
        s1 += __shfl_xor_sync(0xffffffffu, s1, 1);
        s1 += __shfl_xor_sync(0xffffffffu, s1, 2);
        l0 = l0 * cr0 + s0;
        l1 = l1 * cr1 + s1;
        m0 = mn0; m1 = mn1;

#pragma unroll
        for (int nt = 0; nt < 16; nt++) {
            oacc[nt][0] *= cr0; oacc[nt][1] *= cr0;
            oacc[nt][2] *= cr1; oacc[nt][3] *= cr1;
        }
        __syncwarp();

#pragma unroll
        for (int kk = 0; kk < 8; kk++) {
            uint32_t a[4];
            const uint32_t* pp = sPw + lane4 * APP + kk * 8 + lanek;
            a[0] = pp[0]; a[1] = pp[8 * APP]; a[2] = pp[4]; a[3] = pp[8 * APP + 4];
#pragma unroll
            for (int nt = 0; nt < 16; nt++) {
                uint32_t bb[2];
                const uint32_t* vp = sVu + (kk * 8 + lanek) * ADP + nt * 8 + lane4;
                bb[0] = vp[0]; bb[1] = vp[4 * ADP];
                mma_tf32(oacc[nt], a, bb);
            }
        }
        __syncwarp();
    }

    // Epilogue: normalize and emit fp16 for the O projection
    float i0 = 1.f / l0, i1 = 1.f / l1;
    int row0 = q0 + w * 16 + lane4;
    __half* O0 = AO + ((size_t)(b * S_ + row0) * H_ + h) * D_;
    __half* O1 = O0 + (size_t)8 * H_ * D_;
#pragma unroll
    for (int nt = 0; nt < 16; nt++) {
        int col = nt * 8 + 2 * lanek;
        __half2 lo = __floats2half2_rn(oacc[nt][0] * i0, oacc[nt][1] * i0);
        __half2 hi = __floats2half2_rn(oacc[nt][2] * i1, oacc[nt][3] * i1);
        *(__half2*)&O0[col] = lo;
        *(__half2*)&O1[col] = hi;
    }
}

// ---------------------------------------------------------------------------
extern "C" void kernel_launch(void* const* d_in, const int* in_sizes, int n_in,
                              void* d_out, int out_size)
{
    const float* hidden = (const float*)d_in[0];
    const float* cosb   = (const float*)d_in[1];
    const float* sinb   = (const float*)d_in[2];
    const float* qkv_w  = (const float*)d_in[3];
    const float* o_w    = (const float*)d_in[4];
    const float* qnw    = (const float*)d_in[5];
    const float* knw    = (const float*)d_in[6];
    float* out = (float*)d_out;

    float  *qkvp;
    __half *aop, *htp, *w1p, *w2p;
    cudaGetSymbolAddress((void**)&qkvp, g_qkv);
    cudaGetSymbolAddress((void**)&aop,  g_ao);
    cudaGetSymbolAddress((void**)&htp,  g_ht);
    cudaGetSymbolAddress((void**)&w1p,  g_w1);
    cudaGetSymbolAddress((void**)&w2p,  g_w2);

    cudaFuncSetAttribute(gemm_f16, cudaFuncAttributeMaxDynamicSharedMemorySize,
                         G_DYN_SMEM);
    cudaFuncSetAttribute(flash_attn_mma, cudaFuncAttributeMaxDynamicSharedMemorySize,
                         ATTN_SMEM);

    // 0) One-time fp16 pre-convert of GEMM inputs
    int nh = MTOK * HID_ / 4, nw1 = QKVN * HID_ / 4, nw2 = HID_ * HID_ / 4;
    cvt_f16<<<(nh  + 255) / 256, 256>>>(hidden, htp, nh);
    cvt_f16<<<(nw1 + 255) / 256, 256>>>(qkv_w,  w1p, nw1);
    cvt_f16<<<(nw2 + 255) / 256, 256>>>(o_w,    w2p, nw2);

    // 1) QKV projection (fp16 m16n8k16, R12 structure, BK=32)
    dim3 g1(QKVN / GBN, MTOK / GBM);
    gemm_f16<<<g1, 256, G_DYN_SMEM>>>(htp, w1p, qkvp, MTOK, QKVN, HID_);

    // 2) RoPE + RMSNorm + scatter (tf32 bits for attention)
    rope_norm<<<MTOK, 128>>>(cosb, sinb, qnw, knw);

    // 3) Attention (tf32 mma.sync flash, BR=128; emits fp16 AO)
    dim3 g3(S_ / FBR, H_, B_);
    flash_attn_mma<<<g3, 256, ATTN_SMEM>>>(aop);

    // 4) O projection (fp16)
    dim3 g4(HID_ / GBN, MTOK / GBM);
    gemm_f16<<<g4, 256, G_DYN_SMEM>>>(aop, w2p, out, MTOK, HID_, H_ * D_);
}

// round 14
// speedup vs baseline: 2.4159x; 1.1186x over previous
#include <cuda_runtime.h>
#include <cuda_fp16.h>
#include <cstdint>
#include <math.h>

// Problem constants
#define B_    2
#define S_    2048
#define HID_  4096
#define H_    32
#define KVH_  8
#define D_    128
#define NREP  (H_/KVH_)                 // 4
#define QKVN  (HID_ + 2*KVH_*D_)        // 6144
#define MTOK  (B_*S_)                   // 4096

// Scratch (static device globals; no runtime allocation allowed)
__device__ float  g_qkv[(size_t)MTOK * QKVN];           // [tok][6144] fp32
__device__ __half g_q  [(size_t)B_*H_*S_*D_];           // fp16, pre-scaled
__device__ __half g_k  [(size_t)B_*KVH_*S_*D_];         // fp16
__device__ __half g_v  [(size_t)B_*KVH_*S_*D_];         // fp16 [key][d]
__device__ __half g_vt [(size_t)B_*KVH_*D_*S_];         // fp16 [d][key]
__device__ __half g_ao [(size_t)MTOK * H_*D_];          // fp16 (O-GEMM input)
__device__ __half g_ht [(size_t)MTOK * HID_];           // hidden, fp16
__device__ __half g_w1 [(size_t)QKVN * HID_];           // qkv_w, fp16
__device__ __half g_w2 [(size_t)HID_ * HID_];           // o_w, fp16

__device__ __forceinline__ float ex2f(float x) {
    float y;
    asm("ex2.approx.f32 %0, %1;" : "=f"(y) : "f"(x));
    return y;
}
__device__ __forceinline__ void mma_f16(float* c, const uint32_t* a, const uint32_t* b) {
    asm volatile(
        "mma.sync.aligned.m16n8k16.row.col.f32.f16.f16.f32 "
        "{%0,%1,%2,%3}, {%4,%5,%6,%7}, {%8,%9}, {%0,%1,%2,%3};"
        : "+f"(c[0]), "+f"(c[1]), "+f"(c[2]), "+f"(c[3])
        : "r"(a[0]), "r"(a[1]), "r"(a[2]), "r"(a[3]), "r"(b[0]), "r"(b[1]));
}
__device__ __forceinline__ void cp_async16(uint32_t saddr, const void* gaddr) {
    asm volatile("cp.async.cg.shared.global [%0], [%1], 16;"
                 :: "r"(saddr), "l"(gaddr) : "memory");
}

// ---------------------------------------------------------------------------
// One-time fp16 pre-convert of GEMM inputs (vectorized)
// ---------------------------------------------------------------------------
__global__ __launch_bounds__(256) void cvt_f16(
    const float* __restrict__ in, __half* __restrict__ out, int n4)
{
    int i = blockIdx.x * 256 + threadIdx.x;
    if (i >= n4) return;
    float4 v = ((const float4*)in)[i];
    __half2 h01 = __floats2half2_rn(v.x, v.y);
    __half2 h23 = __floats2half2_rn(v.z, v.w);
    uint2 u;
    u.x = *(uint32_t*)&h01;
    u.y = *(uint32_t*)&h23;
    ((uint2*)out)[i] = u;
}

// ===========================================================================
// fp16 mma.sync GEMM (NT) — R13 version (unchanged; best measured).
// ===========================================================================
#define GBM 128
#define GBN 128
#define GBK 32
#define GSTRIDE 20
#define G_TILE_U32 (128 * GSTRIDE)
#define G_STAGE_U32 (2 * G_TILE_U32)
#define G_NSTAGE 3
#define G_DYN_SMEM (G_NSTAGE * G_STAGE_U32 * 4)

__global__ __launch_bounds__(256) void gemm_f16(
    const __half* __restrict__ A, const __half* __restrict__ Bm,
    float* __restrict__ C, int M, int N, int K)
{
    extern __shared__ uint32_t sdyn[];
    const uint32_t sbase = (uint32_t)__cvta_generic_to_shared(sdyn);

    const int tid  = threadIdx.x;
    const int wid  = tid >> 5;
    const int lane = tid & 31;
    const int warp_m = wid >> 2;
    const int warp_n = wid & 3;
    const int lane4 = lane >> 2;
    const int lanek = lane & 3;
    const int m0 = blockIdx.y * GBM;
    const int n0 = blockIdx.x * GBN;
    const int NK = K >> 5;

    const int r  = tid >> 1;
    const int c0 = (tid & 1) * 2;
    const __half* Ag = A  + (size_t)(m0 + r) * K;
    const __half* Bg = Bm + (size_t)(n0 + r) * K;
    const uint32_t sArow = sbase + (uint32_t)r * (GSTRIDE * 4);
    const uint32_t sBrow = sArow + G_TILE_U32 * 4;

#pragma unroll
    for (int s = 0; s < G_NSTAGE; s++) {
        uint32_t so = (uint32_t)s * (G_STAGE_U32 * 4);
        const __half* ag = Ag + s * GBK;
        const __half* bg = Bg + s * GBK;
        cp_async16(sArow + so + (c0    ) * 16, ag + (c0    ) * 8);
        cp_async16(sArow + so + (c0 + 1) * 16, ag + (c0 + 1) * 8);
        cp_async16(sBrow + so + (c0    ) * 16, bg + (c0    ) * 8);
        cp_async16(sBrow + so + (c0 + 1) * 16, bg + (c0 + 1) * 8);
        asm volatile("cp.async.commit_group;" ::: "memory");
    }

    float acc[4][4][4];
#pragma unroll
    for (int i = 0; i < 4; i++)
#pragma unroll
        for (int j = 0; j < 4; j++)
#pragma unroll
            for (int t = 0; t < 4; t++) acc[i][j][t] = 0.f;

    for (int it = 0; it < NK; it++) {
        asm volatile("cp.async.wait_group %0;" :: "n"(G_NSTAGE - 1) : "memory");
        __syncthreads();

        const uint32_t* sA = sdyn + (it % G_NSTAGE) * G_STAGE_U32;
        const uint32_t* sB = sA + G_TILE_U32;

#pragma unroll
        for (int ks = 0; ks < 2; ks++) {
            const int kb = ks * 8 + lanek;
            uint32_t af[4][4], bf[4][2];
#pragma unroll
            for (int mt = 0; mt < 4; mt++) {
                const uint32_t* ap = sA + (warp_m * 64 + mt * 16 + lane4) * GSTRIDE + kb;
                af[mt][0] = ap[0];
                af[mt][1] = ap[8 * GSTRIDE];
                af[mt][2] = ap[4];
                af[mt][3] = ap[8 * GSTRIDE + 4];
            }
#pragma unroll
            for (int nt = 0; nt < 4; nt++) {
                const uint32_t* bp = sB + (warp_n * 32 + nt * 8 + lane4) * GSTRIDE + kb;
                bf[nt][0] = bp[0];
                bf[nt][1] = bp[4];
            }
#pragma unroll
            for (int mt = 0; mt < 4; mt++)
#pragma unroll
                for (int nt = 0; nt < 4; nt++)
                    mma_f16(acc[mt][nt], af[mt], bf[nt]);
        }

        __syncthreads();

        int itn = it + G_NSTAGE;
        if (itn < NK) {
            uint32_t so = (uint32_t)(itn % G_NSTAGE) * (G_STAGE_U32 * 4);
            const __half* ag = Ag + itn * GBK;
            const __half* bg = Bg + itn * GBK;
            cp_async16(sArow + so + (c0    ) * 16, ag + (c0    ) * 8);
            cp_async16(sArow + so + (c0 + 1) * 16, ag + (c0 + 1) * 8);
            cp_async16(sBrow + so + (c0    ) * 16, bg + (c0    ) * 8);
            cp_async16(sBrow + so + (c0 + 1) * 16, bg + (c0 + 1) * 8);
        }
        asm volatile("cp.async.commit_group;" ::: "memory");
    }

#pragma unroll
    for (int mt = 0; mt < 4; mt++) {
#pragma unroll
        for (int nt = 0; nt < 4; nt++) {
            int row = m0 + warp_m * 64 + mt * 16 + lane4;
            int col = n0 + warp_n * 32 + nt * 8 + lanek * 2;
            *(float2*)&C[(size_t)row * N + col] =
                make_float2(acc[mt][nt][0], acc[mt][nt][1]);
            *(float2*)&C[(size_t)(row + 8) * N + col] =
                make_float2(acc[mt][nt][2], acc[mt][nt][3]);
        }
    }
}

// ---------------------------------------------------------------------------
// RoPE + per-head RMSNorm + scatter, one block per TOKEN. Emits fp16
// (Q pre-scaled by scale*log2e).
// ---------------------------------------------------------------------------
__global__ __launch_bounds__(128) void rope_norm(
    const float* __restrict__ cosb, const float* __restrict__ sinb,
    const float* __restrict__ qw,   const float* __restrict__ kw)
{
    const int tok = blockIdx.x;
    const int b = tok / S_, s = tok % S_;
    const int tid = threadIdx.x;
    const int w = tid >> 5, lane = tid & 31;
    const float QSC = 0.08838834764831845f * 1.4426950408889634f;

    const float* row = g_qkv + (size_t)tok * QKVN;
    float c4[4], s4[4], qw4[4], kw4[4];
#pragma unroll
    for (int j = 0; j < 4; j++) {
        int d = lane + 32 * j;
        c4[j]  = cosb[((size_t)b * S_ + s) * D_ + d];
        s4[j]  = sinb[((size_t)b * S_ + s) * D_ + d];
        qw4[j] = qw[d];
        kw4[j] = kw[d];
    }

    for (int hh = w; hh < H_ + KVH_; hh += 4) {
        int off = (hh < H_) ? hh * D_ : H_ * D_ + (hh - H_) * D_;
        float x[4], y[4];
#pragma unroll
        for (int j = 0; j < 4; j++) x[j] = row[off + lane + 32 * j];
        y[0] = x[0] * c4[0] - x[2] * s4[0];
        y[1] = x[1] * c4[1] - x[3] * s4[1];
        y[2] = x[2] * c4[2] + x[0] * s4[2];
        y[3] = x[3] * c4[3] + x[1] * s4[3];
        float v2 = y[0] * y[0] + y[1] * y[1] + y[2] * y[2] + y[3] * y[3];
#pragma unroll
        for (int o = 16; o; o >>= 1) v2 += __shfl_xor_sync(0xffffffffu, v2, o);
        float inv = rsqrtf(v2 * (1.f / D_) + 1e-6f);

        if (hh < H_) {
            __half* dst = g_q + (((size_t)b * H_ + hh) * S_ + s) * D_;
#pragma unroll
            for (int j = 0; j < 4; j++)
                dst[lane + 32 * j] = __float2half(qw4[j] * y[j] * inv * QSC);
        } else {
            __half* dst = g_k + (((size_t)b * KVH_ + (hh - H_)) * S_ + s) * D_;
#pragma unroll
            for (int j = 0; j < 4; j++)
                dst[lane + 32 * j] = __float2half(kw4[j] * y[j] * inv);
        }
    }

    for (int kv = w; kv < KVH_; kv += 4) {
        const float* src = row + H_ * D_ + KVH_ * D_ + kv * D_;
        __half* dst = g_v + (((size_t)b * KVH_ + kv) * S_ + s) * D_;
#pragma unroll
        for (int j = 0; j < 4; j++)
            dst[lane + 32 * j] = __float2half(src[lane + 32 * j]);
    }
}

// ---------------------------------------------------------------------------
// V transpose: g_v [bkv][s][d] -> g_vt [bkv][d][s]. 32x32 smem tiles.
// ---------------------------------------------------------------------------
__global__ __launch_bounds__(256) void v_transpose()
{
    __shared__ __half t[32][33];
    const int bkv = blockIdx.z;
    const int s0 = blockIdx.x * 32;
    const int d0 = blockIdx.y * 32;
    const int tx = threadIdx.x, ty = threadIdx.y;   // block (32, 8)

    const __half* src = g_v  + (size_t)bkv * S_ * D_;
    __half*       dst = g_vt + (size_t)bkv * D_ * S_;

#pragma unroll
    for (int j = 0; j < 32; j += 8)
        t[ty + j][tx] = src[(size_t)(s0 + ty + j) * D_ + d0 + tx];
    __syncthreads();
#pragma unroll
    for (int j = 0; j < 32; j += 8)
        dst[(size_t)(d0 + ty + j) * S_ + s0 + tx] = t[tx][ty + j];
}

// ---------------------------------------------------------------------------
// Flash attention, fp16 m16n8k16. BR=128 (8 warps, 256 thr), BC=64, D=128.
// Q/K fp16 rows (stride 68 u32); V via pre-transposed g_vt (stride 36 u32);
// P stored as half2 pairs (stride 36 u32). All fragment loads conflict-free.
// smem 89 KB -> up to 2 CTAs/SM. Output fp16 -> g_ao.
// ---------------------------------------------------------------------------
#define FBR 128
#define QKP 68     // Q/K row stride (u32)
#define VTP 36     // Vt / P row stride (u32)
#define SQ_U  (FBR * QKP)        // 8704
#define SK_U  (64 * QKP)         // 4352
#define SVT_U (128 * VTP)        // 4608
#define SP_U  (8 * 16 * VTP)     // 4608
#define ATTN_SMEM ((SQ_U + SK_U + SVT_U + SP_U) * 4)   // 89088 B

__global__ __launch_bounds__(256) void flash_attn_f16(__half* __restrict__ AO)
{
    extern __shared__ uint32_t smu[];
    uint32_t* sQ  = smu;                 // 128 x 68
    uint32_t* sK  = sQ + SQ_U;           // 64 x 68
    uint32_t* sVt = sK + SK_U;           // 128 x 36 (rows = d, cols = key)
    uint32_t* sP  = sVt + SVT_U;         // 8 warps x 16 x 36

    const int b  = blockIdx.z, h = blockIdx.y;
    const int q0 = blockIdx.x * FBR;
    const int kh = h / NREP;
    const __half* Qg  = g_q  + (((size_t)b * H_ + h) * S_ + q0) * D_;
    const __half* Kg  = g_k  + ((size_t)b * KVH_ + kh) * (size_t)S_ * D_;
    const __half* Vtg = g_vt + ((size_t)b * KVH_ + kh) * (size_t)D_ * S_;

    const int tid  = threadIdx.x;
    const int w    = tid >> 5;
    const int lane = tid & 31;
    const int lane4 = lane >> 2;
    const int lanek = lane & 3;

    // Load Q tile: 128 rows x 16 uint4
    for (int e = tid; e < FBR * 16; e += 256) {
        int r = e >> 4, c = e & 15;
        *(uint4*)&sQ[r * QKP + c * 4] = ((const uint4*)Qg)[r * 16 + c];
    }

    float oacc[16][4];
#pragma unroll
    for (int nt = 0; nt < 16; nt++)
#pragma unroll
        for (int t = 0; t < 4; t++) oacc[nt][t] = 0.f;
    float m0 = -1e30f, m1 = -1e30f, l0 = 0.f, l1 = 0.f;

    uint32_t* sPw = sP + w * (16 * VTP);

    for (int t0 = 0; t0 < S_; t0 += 64) {
        __syncthreads();
        // K tile: 64 rows x 16 uint4
        for (int e = tid; e < 64 * 16; e += 256) {
            int r = e >> 4, c = e & 15;
            *(uint4*)&sK[r * QKP + c * 4] =
                ((const uint4*)(Kg + (size_t)t0 * D_))[r * 16 + c];
        }
        // Vt tile: 128 rows (d) x 8 uint4 (64 keys)
        for (int e = tid; e < 128 * 8; e += 256) {
            int r = e >> 3, c = e & 7;
            *(uint4*)&sVt[r * VTP + c * 4] =
                ((const uint4*)(Vtg + (size_t)r * S_ + t0))[c];
        }
        __syncthreads();

        // ---- QK^T (fp16, kk = 8 steps of k16)
        float sc[8][4];
#pragma unroll
        for (int nt = 0; nt < 8; nt++)
#pragma unroll
            for (int t = 0; t < 4; t++) sc[nt][t] = 0.f;

#pragma unroll
        for (int kk = 0; kk < 8; kk++) {
            uint32_t a[4];
            const uint32_t* qp = sQ + (w * 16 + lane4) * QKP + kk * 8 + lanek;
            a[0] = qp[0]; a[1] = qp[8 * QKP]; a[2] = qp[4]; a[3] = qp[8 * QKP + 4];
#pragma unroll
            for (int nt = 0; nt < 8; nt++) {
                uint32_t bb[2];
                const uint32_t* kp = sK + (nt * 8 + lane4) * QKP + kk * 8 + lanek;
                bb[0] = kp[0]; bb[1] = kp[4];
                mma_f16(sc[nt], a, bb);
            }
        }

        // ---- online softmax (log2 domain)
        float mx0 = -1e30f, mx1 = -1e30f;
#pragma unroll
        for (int nt = 0; nt < 8; nt++) {
            mx0 = fmaxf(mx0, fmaxf(sc[nt][0], sc[nt][1]));
            mx1 = fmaxf(mx1, fmaxf(sc[nt][2], sc[nt][3]));
        }
        mx0 = fmaxf(mx0, __shfl_xor_sync(0xffffffffu, mx0, 1));
        mx0 = fmaxf(mx0, __shfl_xor_sync(0xffffffffu, mx0, 2));
        mx1 = fmaxf(mx1, __shfl_xor_sync(0xffffffffu, mx1, 1));
        mx1 = fmaxf(mx1, __shfl_xor_sync(0xffffffffu, mx1, 2));
        float mn0 = fmaxf(m0, mx0), mn1 = fmaxf(m1, mx1);
        float cr0 = ex2f(m0 - mn0), cr1 = ex2f(m1 - mn1);

        float s0 = 0.f, s1 = 0.f;
#pragma unroll
        for (int nt = 0; nt < 8; nt++) {
            float p00 = ex2f(sc[nt][0] - mn0);
            float p01 = ex2f(sc[nt][1] - mn0);
            float p10 = ex2f(sc[nt][2] - mn1);
            float p11 = ex2f(sc[nt][3] - mn1);
            s0 += p00 + p01;
            s1 += p10 + p11;
            __half2 lo = __floats2half2_rn(p00, p01);
            __half2 hi = __floats2half2_rn(p10, p11);
            sPw[lane4 * VTP + nt * 4 + lanek]       = *(uint32_t*)&lo;
            sPw[(lane4 + 8) * VTP + nt * 4 + lanek] = *(uint32_t*)&hi;
        }
        s0 += __shfl_xor_sync(0xffffffffu, s0, 1);
        s0 += __shfl_xor_sync(0xffffffffu, s0, 2);
        s1 += __shfl_xor_sync(0xffffffffu, s1, 1);
        s1 += __shfl_xor_sync(0xffffffffu, s1, 2);
        l0 = l0 * cr0 + s0;
        l1 = l1 * cr1 + s1;
        m0 = mn0; m1 = mn1;

#pragma unroll
        for (int nt = 0; nt < 16; nt++) {
            oacc[nt][0] *= cr0; oacc[nt][1] *= cr0;
            oacc[nt][2] *= cr1; oacc[nt][3] *= cr1;
        }
        __syncwarp();

        // ---- P @ V (fp16): kk = 4 steps of k16 over 64 keys, nt = d-block
#pragma unroll
        for (int kk = 0; kk < 4; kk++) {
            uint32_t a[4];
            const uint32_t* pp = sPw + lane4 * VTP + kk * 8 + lanek;
            a[0] = pp[0]; a[1] = pp[8 * VTP]; a[2] = pp[4]; a[3] = pp[8 * VTP + 4];
#pragma unroll
            for (int nt = 0; nt < 16; nt++) {
                uint32_t bb[2];
                const uint32_t* vp = sVt + (nt * 8 + lane4) * VTP + kk * 8 + lanek;
                bb[0] = vp[0]; bb[1] = vp[4];
                mma_f16(oacc[nt], a, bb);
            }
        }
        __syncwarp();
    }

    float i0 = 1.f / l0, i1 = 1.f / l1;
    int row0 = q0 + w * 16 + lane4;
    __half* O0 = AO + ((size_t)(b * S_ + row0) * H_ + h) * D_;
    __half* O1 = O0 + (size_t)8 * H_ * D_;
#pragma unroll
    for (int nt = 0; nt < 16; nt++) {
        int col = nt * 8 + 2 * lanek;
        __half2 lo = __floats2half2_rn(oacc[nt][0] * i0, oacc[nt][1] * i0);
        __half2 hi = __floats2half2_rn(oacc[nt][2] * i1, oacc[nt][3] * i1);
        *(__half2*)&O0[col] = lo;
        *(__half2*)&O1[col] = hi;
    }
}

// ---------------------------------------------------------------------------
extern "C" void kernel_launch(void* const* d_in, const int* in_sizes, int n_in,
                              void* d_out, int out_size)
{
    const float* hidden = (const float*)d_in[0];
    const float* cosb   = (const float*)d_in[1];
    const float* sinb   = (const float*)d_in[2];
    const float* qkv_w  = (const float*)d_in[3];
    const float* o_w    = (const float*)d_in[4];
    const float* qnw    = (const float*)d_in[5];
    const float* knw    = (const float*)d_in[6];
    float* out = (float*)d_out;

    float  *qkvp;
    __half *aop, *htp, *w1p, *w2p;
    cudaGetSymbolAddress((void**)&qkvp, g_qkv);
    cudaGetSymbolAddress((void**)&aop,  g_ao);
    cudaGetSymbolAddress((void**)&htp,  g_ht);
    cudaGetSymbolAddress((void**)&w1p,  g_w1);
    cudaGetSymbolAddress((void**)&w2p,  g_w2);

    cudaFuncSetAttribute(gemm_f16, cudaFuncAttributeMaxDynamicSharedMemorySize,
                         G_DYN_SMEM);
    cudaFuncSetAttribute(flash_attn_f16, cudaFuncAttributeMaxDynamicSharedMemorySize,
                         ATTN_SMEM);

    // 0) One-time fp16 pre-convert of GEMM inputs
    int nh = MTOK * HID_ / 4, nw1 = QKVN * HID_ / 4, nw2 = HID_ * HID_ / 4;
    cvt_f16<<<(nh  + 255) / 256, 256>>>(hidden, htp, nh);
    cvt_f16<<<(nw1 + 255) / 256, 256>>>(qkv_w,  w1p, nw1);
    cvt_f16<<<(nw2 + 255) / 256, 256>>>(o_w,    w2p, nw2);

    // 1) QKV projection (fp16 m16n8k16)
    dim3 g1(QKVN / GBN, MTOK / GBM);
    gemm_f16<<<g1, 256, G_DYN_SMEM>>>(htp, w1p, qkvp, MTOK, QKVN, HID_);

    // 2) RoPE + RMSNorm + scatter (fp16 outputs)
    rope_norm<<<MTOK, 128>>>(cosb, sinb, qnw, knw);

    // 2b) V transpose for PV fragments
    dim3 gt(S_ / 32, D_ / 32, B_ * KVH_);
    v_transpose<<<gt, dim3(32, 8)>>>();

    // 3) Attention (fp16 m16n8k16 flash, BR=128)
    dim3 g3(S_ / FBR, H_, B_);
    flash_attn_f16<<<g3, 256, ATTN_SMEM>>>(aop);

    // 4) O projection (fp16)
    dim3 g4(HID_ / GBN, MTOK / GBM);
    gemm_f16<<<g4, 256, G_DYN_SMEM>>>(aop, w2p, out, MTOK, HID_, H_ * D_);
}

// round 17
// speedup vs baseline: 2.9403x; 1.2171x over previous
#include <cuda_runtime.h>
#include <cuda_fp16.h>
#include <cstdint>
#include <math.h>

// Problem constants
#define B_    2
#define S_    2048
#define HID_  4096
#define H_    32
#define KVH_  8
#define D_    128
#define NREP  (H_/KVH_)                 // 4
#define QKVN  (HID_ + 2*KVH_*D_)        // 6144
#define MTOK  (B_*S_)                   // 4096

// Scratch (static device globals; no runtime allocation allowed)
__device__ float  g_qkv[(size_t)MTOK * QKVN];           // [tok][6144] fp32
__device__ __half g_q  [(size_t)B_*H_*S_*D_];           // fp16, pre-scaled
__device__ __half g_k  [(size_t)B_*KVH_*S_*D_];         // fp16
__device__ __half g_v  [(size_t)B_*KVH_*S_*D_];         // fp16 [key][d]
__device__ __half g_vt [(size_t)B_*KVH_*D_*S_];         // fp16 [d][key]
__device__ __half g_ao [(size_t)MTOK * H_*D_];          // fp16 (O-GEMM input)
__device__ __half g_ht [(size_t)MTOK * HID_];           // hidden, fp16
__device__ __half g_w1 [(size_t)QKVN * HID_];           // qkv_w, fp16
__device__ __half g_w2 [(size_t)HID_ * HID_];           // o_w, fp16

__device__ __forceinline__ float ex2f(float x) {
    float y;
    asm("ex2.approx.f32 %0, %1;" : "=f"(y) : "f"(x));
    return y;
}
__device__ __forceinline__ void mma_f16(float* c, const uint32_t* a, const uint32_t* b) {
    asm volatile(
        "mma.sync.aligned.m16n8k16.row.col.f32.f16.f16.f32 "
        "{%0,%1,%2,%3}, {%4,%5,%6,%7}, {%8,%9}, {%0,%1,%2,%3};"
        : "+f"(c[0]), "+f"(c[1]), "+f"(c[2]), "+f"(c[3])
        : "r"(a[0]), "r"(a[1]), "r"(a[2]), "r"(a[3]), "r"(b[0]), "r"(b[1]));
}
__device__ __forceinline__ void cp_async16(uint32_t saddr, const void* gaddr) {
    asm volatile("cp.async.cg.shared.global [%0], [%1], 16;"
                 :: "r"(saddr), "l"(gaddr) : "memory");
}

// ---------------------------------------------------------------------------
// One-time fp16 pre-convert of GEMM inputs (vectorized)
// ---------------------------------------------------------------------------
__global__ __launch_bounds__(256) void cvt_f16(
    const float* __restrict__ in, __half* __restrict__ out, int n4)
{
    int i = blockIdx.x * 256 + threadIdx.x;
    if (i >= n4) return;
    float4 v = ((const float4*)in)[i];
    __half2 h01 = __floats2half2_rn(v.x, v.y);
    __half2 h23 = __floats2half2_rn(v.z, v.w);
    uint2 u;
    u.x = *(uint32_t*)&h01;
    u.y = *(uint32_t*)&h23;
    ((uint2*)out)[i] = u;
}

// ===========================================================================
// fp16 mma.sync GEMM (NT) — R13/R14 version (frozen; measured best).
// ===========================================================================
#define GBM 128
#define GBN 128
#define GBK 32
#define GSTRIDE 20
#define G_TILE_U32 (128 * GSTRIDE)
#define G_STAGE_U32 (2 * G_TILE_U32)
#define G_NSTAGE 3
#define G_DYN_SMEM (G_NSTAGE * G_STAGE_U32 * 4)

__global__ __launch_bounds__(256) void gemm_f16(
    const __half* __restrict__ A, const __half* __restrict__ Bm,
    float* __restrict__ C, int M, int N, int K)
{
    extern __shared__ uint32_t sdyn[];
    const uint32_t sbase = (uint32_t)__cvta_generic_to_shared(sdyn);

    const int tid  = threadIdx.x;
    const int wid  = tid >> 5;
    const int lane = tid & 31;
    const int warp_m = wid >> 2;
    const int warp_n = wid & 3;
    const int lane4 = lane >> 2;
    const int lanek = lane & 3;
    const int m0 = blockIdx.y * GBM;
    const int n0 = blockIdx.x * GBN;
    const int NK = K >> 5;

    const int r  = tid >> 1;
    const int c0 = (tid & 1) * 2;
    const __half* Ag = A  + (size_t)(m0 + r) * K;
    const __half* Bg = Bm + (size_t)(n0 + r) * K;
    const uint32_t sArow = sbase + (uint32_t)r * (GSTRIDE * 4);
    const uint32_t sBrow = sArow + G_TILE_U32 * 4;

#pragma unroll
    for (int s = 0; s < G_NSTAGE; s++) {
        uint32_t so = (uint32_t)s * (G_STAGE_U32 * 4);
        const __half* ag = Ag + s * GBK;
        const __half* bg = Bg + s * GBK;
        cp_async16(sArow + so + (c0    ) * 16, ag + (c0    ) * 8);
        cp_async16(sArow + so + (c0 + 1) * 16, ag + (c0 + 1) * 8);
        cp_async16(sBrow + so + (c0    ) * 16, bg + (c0    ) * 8);
        cp_async16(sBrow + so + (c0 + 1) * 16, bg + (c0 + 1) * 8);
        asm volatile("cp.async.commit_group;" ::: "memory");
    }

    float acc[4][4][4];
#pragma unroll
    for (int i = 0; i < 4; i++)
#pragma unroll
        for (int j = 0; j < 4; j++)
#pragma unroll
            for (int t = 0; t < 4; t++) acc[i][j][t] = 0.f;

    for (int it = 0; it < NK; it++) {
        asm volatile("cp.async.wait_group %0;" :: "n"(G_NSTAGE - 1) : "memory");
        __syncthreads();

        const uint32_t* sA = sdyn + (it % G_NSTAGE) * G_STAGE_U32;
        const uint32_t* sB = sA + G_TILE_U32;

#pragma unroll
        for (int ks = 0; ks < 2; ks++) {
            const int kb = ks * 8 + lanek;
            uint32_t af[4][4], bf[4][2];
#pragma unroll
            for (int mt = 0; mt < 4; mt++) {
                const uint32_t* ap = sA + (warp_m * 64 + mt * 16 + lane4) * GSTRIDE + kb;
                af[mt][0] = ap[0];
                af[mt][1] = ap[8 * GSTRIDE];
                af[mt][2] = ap[4];
                af[mt][3] = ap[8 * GSTRIDE + 4];
            }
#pragma unroll
            for (int nt = 0; nt < 4; nt++) {
                const uint32_t* bp = sB + (warp_n * 32 + nt * 8 + lane4) * GSTRIDE + kb;
                bf[nt][0] = bp[0];
                bf[nt][1] = bp[4];
            }
#pragma unroll
            for (int mt = 0; mt < 4; mt++)
#pragma unroll
                for (int nt = 0; nt < 4; nt++)
                    mma_f16(acc[mt][nt], af[mt], bf[nt]);
        }

        __syncthreads();

        int itn = it + G_NSTAGE;
        if (itn < NK) {
            uint32_t so = (uint32_t)(itn % G_NSTAGE) * (G_STAGE_U32 * 4);
            const __half* ag = Ag + itn * GBK;
            const __half* bg = Bg + itn * GBK;
            cp_async16(sArow + so + (c0    ) * 16, ag + (c0    ) * 8);
            cp_async16(sArow + so + (c0 + 1) * 16, ag + (c0 + 1) * 8);
            cp_async16(sBrow + so + (c0    ) * 16, bg + (c0    ) * 8);
            cp_async16(sBrow + so + (c0 + 1) * 16, bg + (c0 + 1) * 8);
        }
        asm volatile("cp.async.commit_group;" ::: "memory");
    }

#pragma unroll
    for (int mt = 0; mt < 4; mt++) {
#pragma unroll
        for (int nt = 0; nt < 4; nt++) {
            int row = m0 + warp_m * 64 + mt * 16 + lane4;
            int col = n0 + warp_n * 32 + nt * 8 + lanek * 2;
            *(float2*)&C[(size_t)row * N + col] =
                make_float2(acc[mt][nt][0], acc[mt][nt][1]);
            *(float2*)&C[(size_t)(row + 8) * N + col] =
                make_float2(acc[mt][nt][2], acc[mt][nt][3]);
        }
    }
}

// ---------------------------------------------------------------------------
// RoPE + per-head RMSNorm + scatter, one block per TOKEN. Emits fp16
// (Q pre-scaled by scale*log2e).
// ---------------------------------------------------------------------------
__global__ __launch_bounds__(128) void rope_norm(
    const float* __restrict__ cosb, const float* __restrict__ sinb,
    const float* __restrict__ qw,   const float* __restrict__ kw)
{
    const int tok = blockIdx.x;
    const int b = tok / S_, s = tok % S_;
    const int tid = threadIdx.x;
    const int w = tid >> 5, lane = tid & 31;
    const float QSC = 0.08838834764831845f * 1.4426950408889634f;

    const float* row = g_qkv + (size_t)tok * QKVN;
    float c4[4], s4[4], qw4[4], kw4[4];
#pragma unroll
    for (int j = 0; j < 4; j++) {
        int d = lane + 32 * j;
        c4[j]  = cosb[((size_t)b * S_ + s) * D_ + d];
        s4[j]  = sinb[((size_t)b * S_ + s) * D_ + d];
        qw4[j] = qw[d];
        kw4[j] = kw[d];
    }

    for (int hh = w; hh < H_ + KVH_; hh += 4) {
        int off = (hh < H_) ? hh * D_ : H_ * D_ + (hh - H_) * D_;
        float x[4], y[4];
#pragma unroll
        for (int j = 0; j < 4; j++) x[j] = row[off + lane + 32 * j];
        y[0] = x[0] * c4[0] - x[2] * s4[0];
        y[1] = x[1] * c4[1] - x[3] * s4[1];
        y[2] = x[2] * c4[2] + x[0] * s4[2];
        y[3] = x[3] * c4[3] + x[1] * s4[3];
        float v2 = y[0] * y[0] + y[1] * y[1] + y[2] * y[2] + y[3] * y[3];
#pragma unroll
        for (int o = 16; o; o >>= 1) v2 += __shfl_xor_sync(0xffffffffu, v2, o);
        float inv = rsqrtf(v2 * (1.f / D_) + 1e-6f);

        if (hh < H_) {
            __half* dst = g_q + (((size_t)b * H_ + hh) * S_ + s) * D_;
#pragma unroll
            for (int j = 0; j < 4; j++)
                dst[lane + 32 * j] = __float2half(qw4[j] * y[j] * inv * QSC);
        } else {
            __half* dst = g_k + (((size_t)b * KVH_ + (hh - H_)) * S_ + s) * D_;
#pragma unroll
            for (int j = 0; j < 4; j++)
                dst[lane + 32 * j] = __float2half(kw4[j] * y[j] * inv);
        }
    }

    for (int kv = w; kv < KVH_; kv += 4) {
        const float* src = row + H_ * D_ + KVH_ * D_ + kv * D_;
        __half* dst = g_v + (((size_t)b * KVH_ + kv) * S_ + s) * D_;
#pragma unroll
        for (int j = 0; j < 4; j++)
            dst[lane + 32 * j] = __float2half(src[lane + 32 * j]);
    }
}

// ---------------------------------------------------------------------------
// V transpose: g_v [bkv][s][d] -> g_vt [bkv][d][s]. 32x32 smem tiles.
// ---------------------------------------------------------------------------
__global__ __launch_bounds__(256) void v_transpose()
{
    __shared__ __half t[32][33];
    const int bkv = blockIdx.z;
    const int s0 = blockIdx.x * 32;
    const int d0 = blockIdx.y * 32;
    const int tx = threadIdx.x, ty = threadIdx.y;   // block (32, 8)

    const __half* src = g_v  + (size_t)bkv * S_ * D_;
    __half*       dst = g_vt + (size_t)bkv * D_ * S_;

#pragma unroll
    for (int j = 0; j < 32; j += 8)
        t[ty + j][tx] = src[(size_t)(s0 + ty + j) * D_ + d0 + tx];
    __syncthreads();
#pragma unroll
    for (int j = 0; j < 32; j += 8)
        dst[(size_t)(d0 + ty + j) * S_ + s0 + tx] = t[tx][ty + j];
}

// ---------------------------------------------------------------------------
// Flash attention, fp16 m16n8k16. BR=128 (8 warps, 256 thr), BC=64, D=128.
// (1) __launch_bounds__(256,2): 2 CTAs/SM. (2) K/Vt tiles via cp.async —
// FIXED loader: each thread copies FOUR 16B chunks per tile (K: 64x16 chunks,
// Vt: 128x8 chunks; 1024 chunks / 256 threads = 4 each).
// ---------------------------------------------------------------------------
#define FBR 128
#define QKP 68     // Q/K row stride (u32)
#define VTP 36     // Vt / P row stride (u32)
#define SQ_U  (FBR * QKP)        // 8704
#define SK_U  (64 * QKP)         // 4352
#define SVT_U (128 * VTP)        // 4608
#define SP_U  (8 * 16 * VTP)     // 4608
#define ATTN_SMEM ((SQ_U + SK_U + SVT_U + SP_U) * 4)   // 89088 B

__global__ __launch_bounds__(256, 2) void flash_attn_f16(__half* __restrict__ AO)
{
    extern __shared__ uint32_t smu[];
    uint32_t* sQ  = smu;                 // 128 x 68
    uint32_t* sK  = sQ + SQ_U;           // 64 x 68
    uint32_t* sVt = sK + SK_U;           // 128 x 36 (rows = d, cols = key)
    uint32_t* sP  = sVt + SVT_U;         // 8 warps x 16 x 36

    const uint32_t sKb  = (uint32_t)__cvta_generic_to_shared(sK);
    const uint32_t sVtb = (uint32_t)__cvta_generic_to_shared(sVt);

    const int b  = blockIdx.z, h = blockIdx.y;
    const int q0 = blockIdx.x * FBR;
    const int kh = h / NREP;
    const __half* Qg  = g_q  + (((size_t)b * H_ + h) * S_ + q0) * D_;
    const __half* Kg  = g_k  + ((size_t)b * KVH_ + kh) * (size_t)S_ * D_;
    const __half* Vtg = g_vt + ((size_t)b * KVH_ + kh) * (size_t)D_ * S_;

    const int tid  = threadIdx.x;
    const int w    = tid >> 5;
    const int lane = tid & 31;
    const int lane4 = lane >> 2;
    const int lanek = lane & 3;

    // cp.async per-thread layout:
    // K tile: row kr (0..63), chunks kc, kc+4, kc+8, kc+12  (16 chunks/row)
    // Vt tile: row vr (0..127), chunks vc, vc+2, vc+4, vc+6 (8 chunks/row)
    const int kr = tid >> 2, kc = tid & 3;
    const int vr = tid >> 1, vc = tid & 1;

    // Load Q tile: 128 rows x 16 uint4
    for (int e = tid; e < FBR * 16; e += 256) {
        int r = e >> 4, c = e & 15;
        *(uint4*)&sQ[r * QKP + c * 4] = ((const uint4*)Qg)[r * 16 + c];
    }

    float oacc[16][4];
#pragma unroll
    for (int nt = 0; nt < 16; nt++)
#pragma unroll
        for (int t = 0; t < 4; t++) oacc[nt][t] = 0.f;
    float m0 = -1e30f, m1 = -1e30f, l0 = 0.f, l1 = 0.f;

    uint32_t* sPw = sP + w * (16 * VTP);

    for (int t0 = 0; t0 < S_; t0 += 64) {
        __syncthreads();   // prev-iter reads of sK/sVt/sP done

        // K tile: 4 chunks per thread
#pragma unroll
        for (int j = 0; j < 4; j++) {
            int c = kc + 4 * j;
            cp_async16(sKb + (uint32_t)(kr * QKP + c * 4) * 4,
                       Kg + (size_t)(t0 + kr) * D_ + c * 8);
        }
        // Vt tile: 4 chunks per thread
#pragma unroll
        for (int j = 0; j < 4; j++) {
            int c = vc + 2 * j;
            cp_async16(sVtb + (uint32_t)(vr * VTP + c * 4) * 4,
                       Vtg + (size_t)vr * S_ + t0 + c * 8);
        }
        asm volatile("cp.async.commit_group;" ::: "memory");
        asm volatile("cp.async.wait_group 0;" ::: "memory");
        __syncthreads();

        // ---- QK^T (fp16, kk = 8 steps of k16)
        float sc[8][4];
#pragma unroll
        for (int nt = 0; nt < 8; nt++)
#pragma unroll
            for (int t = 0; t < 4; t++) sc[nt][t] = 0.f;

#pragma unroll
        for (int kk = 0; kk < 8; kk++) {
            uint32_t a[4];
            const uint32_t* qp = sQ + (w * 16 + lane4) * QKP + kk * 8 + lanek;
            a[0] = qp[0]; a[1] = qp[8 * QKP]; a[2] = qp[4]; a[3] = qp[8 * QKP + 4];
#pragma unroll
            for (int nt = 0; nt < 8; nt++) {
                uint32_t bb[2];
                const uint32_t* kp = sK + (nt * 8 + lane4) * QKP + kk * 8 + lanek;
                bb[0] = kp[0]; bb[1] = kp[4];
                mma_f16(sc[nt], a, bb);
            }
        }

        // ---- online softmax (log2 domain)
        float mx0 = -1e30f, mx1 = -1e30f;
#pragma unroll
        for (int nt = 0; nt < 8; nt++) {
            mx0 = fmaxf(mx0, fmaxf(sc[nt][0], sc[nt][1]));
            mx1 = fmaxf(mx1, fmaxf(sc[nt][2], sc[nt][3]));
        }
        mx0 = fmaxf(mx0, __shfl_xor_sync(0xffffffffu, mx0, 1));
        mx0 = fmaxf(mx0, __shfl_xor_sync(0xffffffffu, mx0, 2));
        mx1 = fmaxf(mx1, __shfl_xor_sync(0xffffffffu, mx1, 1));
        mx1 = fmaxf(mx1, __shfl_xor_sync(0xffffffffu, mx1, 2));
        float mn0 = fmaxf(m0, mx0), mn1 = fmaxf(m1, mx1);
        float cr0 = ex2f(m0 - mn0), cr1 = ex2f(m1 - mn1);

        float s0 = 0.f, s1 = 0.f;
#pragma unroll
        for (int nt = 0; nt < 8; nt++) {
            float p00 = ex2f(sc[nt][0] - mn0);
            float p01 = ex2f(sc[nt][1] - mn0);
            float p10 = ex2f(sc[nt][2] - mn1);
            float p11 = ex2f(sc[nt][3] - mn1);
            s0 += p00 + p01;
            s1 += p10 + p11;
            __half2 lo = __floats2half2_rn(p00, p01);
            __half2 hi = __floats2half2_rn(p10, p11);
            sPw[lane4 * VTP + nt * 4 + lanek]       = *(uint32_t*)&lo;
            sPw[(lane4 + 8) * VTP + nt * 4 + lanek] = *(uint32_t*)&hi;
        }
        s0 += __shfl_xor_sync(0xffffffffu, s0, 1);
        s0 += __shfl_xor_sync(0xffffffffu, s0, 2);
        s1 += __shfl_xor_sync(0xffffffffu, s1, 1);
        s1 += __shfl_xor_sync(0xffffffffu, s1, 2);
        l0 = l0 * cr0 + s0;
        l1 = l1 * cr1 + s1;
        m0 = mn0; m1 = mn1;

#pragma unroll
        for (int nt = 0; nt < 16; nt++) {
            oacc[nt][0] *= cr0; oacc[nt][1] *= cr0;
            oacc[nt][2] *= cr1; oacc[nt][3] *= cr1;
        }
        __syncwarp();

        // ---- P @ V (fp16): kk = 4 steps of k16 over 64 keys, nt = d-block
#pragma unroll
        for (int kk = 0; kk < 4; kk++) {
            uint32_t a[4];
            const uint32_t* pp = sPw + lane4 * VTP + kk * 8 + lanek;
            a[0] = pp[0]; a[1] = pp[8 * VTP]; a[2] = pp[4]; a[3] = pp[8 * VTP + 4];
#pragma unroll
            for (int nt = 0; nt < 16; nt++) {
                uint32_t bb[2];
                const uint32_t* vp = sVt + (nt * 8 + lane4) * VTP + kk * 8 + lanek;
                bb[0] = vp[0]; bb[1] = vp[4];
                mma_f16(oacc[nt], a, bb);
            }
        }
        __syncwarp();
    }

    float i0 = 1.f / l0, i1 = 1.f / l1;
    int row0 = q0 + w * 16 + lane4;
    __half* O0 = AO + ((size_t)(b * S_ + row0) * H_ + h) * D_;
    __half* O1 = O0 + (size_t)8 * H_ * D_;
#pragma unroll
    for (int nt = 0; nt < 16; nt++) {
        int col = nt * 8 + 2 * lanek;
        __half2 lo = __floats2half2_rn(oacc[nt][0] * i0, oacc[nt][1] * i0);
        __half2 hi = __floats2half2_rn(oacc[nt][2] * i1, oacc[nt][3] * i1);
        *(__half2*)&O0[col] = lo;
        *(__half2*)&O1[col] = hi;
    }
}

// ---------------------------------------------------------------------------
extern "C" void kernel_launch(void* const* d_in, const int* in_sizes, int n_in,
                              void* d_out, int out_size)
{
    const float* hidden = (const float*)d_in[0];
    const float* cosb   = (const float*)d_in[1];
    const float* sinb   = (const float*)d_in[2];
    const float* qkv_w  = (const float*)d_in[3];
    const float* o_w    = (const float*)d_in[4];
    const float* qnw    = (const float*)d_in[5];
    const float* knw    = (const float*)d_in[6];
    float* out = (float*)d_out;

    float  *qkvp;
    __half *aop, *htp, *w1p, *w2p;
    cudaGetSymbolAddress((void**)&qkvp, g_qkv);
    cudaGetSymbolAddress((void**)&aop,  g_ao);
    cudaGetSymbolAddress((void**)&htp,  g_ht);
    cudaGetSymbolAddress((void**)&w1p,  g_w1);
    cudaGetSymbolAddress((void**)&w2p,  g_w2);

    cudaFuncSetAttribute(gemm_f16, cudaFuncAttributeMaxDynamicSharedMemorySize,
                         G_DYN_SMEM);
    cudaFuncSetAttribute(flash_attn_f16, cudaFuncAttributeMaxDynamicSharedMemorySize,
                         ATTN_SMEM);

    // 0) One-time fp16 pre-convert of GEMM inputs
    int nh = MTOK * HID_ / 4, nw1 = QKVN * HID_ / 4, nw2 = HID_ * HID_ / 4;
    cvt_f16<<<(nh  + 255) / 256, 256>>>(hidden, htp, nh);
    cvt_f16<<<(nw1 + 255) / 256, 256>>>(qkv_w,  w1p, nw1);
    cvt_f16<<<(nw2 + 255) / 256, 256>>>(o_w,    w2p, nw2);

    // 1) QKV projection (fp16 m16n8k16)
    dim3 g1(QKVN / GBN, MTOK / GBM);
    gemm_f16<<<g1, 256, G_DYN_SMEM>>>(htp, w1p, qkvp, MTOK, QKVN, HID_);

    // 2) RoPE + RMSNorm + scatter (fp16 outputs)
    rope_norm<<<MTOK, 128>>>(cosb, sinb, qnw, knw);

    // 2b) V transpose for PV fragments
    dim3 gt(S_ / 32, D_ / 32, B_ * KVH_);
    v_transpose<<<gt, dim3(32, 8)>>>();

    // 3) Attention (fp16 flash, 2 CTAs/SM, cp.async tiles — fixed loader)
    dim3 g3(S_ / FBR, H_, B_);
    flash_attn_f16<<<g3, 256, ATTN_SMEM>>>(aop);

    // 4) O projection (fp16)
    dim3 g4(HID_ / GBN, MTOK / GBM);
    gemm_f16<<<g4, 256, G_DYN_SMEM>>>(aop, w2p, out, MTOK, HID_, H_ * D_);
}